// round 15
// baseline (speedup 1.0000x reference)
#include <cuda_runtime.h>
#include <cuda_bf16.h>
#include <cstdint>
#include <math.h>

#define NN   50000
#define EE   600000
#define INF_ 512
#define HH   128
#define H3   384
#define BB   64
#define MT   ((NN + 127) / 128)
#define SEGN (4*NN)
#define SCAN_BLKS ((SEGN + 1023)/1024)
#define GRU_GRID ((NN + 31)/32)

// ---------------- device scratch ----------------
__device__ float g_h0   [(size_t)NN*HH];
__device__ float g_hallA[(size_t)4*NN*HH];
__device__ float g_hallB[(size_t)4*NN*HH];
__device__ float g_proj [(size_t)NN*HH];
__device__ float g_q    [(size_t)NN*HH];
__device__ float g_qk   [(size_t)NN*HH];
__device__ float g_fused[(size_t)NN*HH];
__device__ float g_psum[BB*HH];
__device__ unsigned g_pmax[BB*HH];
__device__ float g_cnt [BB];

__device__ int g_deg   [SEGN];
__device__ int g_scanT [SEGN];
__device__ int g_part  [SCAN_BLKS];
__device__ int g_partS [SCAN_BLKS];
__device__ int g_rowptr[SEGN + 1];
__device__ int g_woff  [SEGN];
__device__ int g_csrsrc[EE];

// bf16 frags for proj/q/qk
#define OFF_PROJ 0
#define OFF_QW   16384
#define OFF_KWT  20480
#define FRAG_TOTAL 24576
__device__ uint4 g_frag[FRAG_TOTAL];

// int8 images: per matrix 128K x 384N -> uint4 at (kc*1536 + nt*32 + lane) = {bh0,bh1,bl0,bl1}
__device__ uint4 g_imgW[16u*6144u];   // Wcomb[v][i]
__device__ uint4 g_imgU[ 4u*6144u];   // Whh[v]
__device__ float g_scW [16*384];      // colmax/16256
__device__ float g_scU [ 4*384];

__constant__ int c_v_of_t[13] = {0,1,1,1,2,2,2,3,3,0,0,3,3};

// ---------------- helpers ----------------
__device__ __forceinline__ uint32_t packbf(float a, float b){
    __nv_bfloat162 t = __halves2bfloat162(__float2bfloat16(a), __float2bfloat16(b));
    return *reinterpret_cast<uint32_t*>(&t);
}
__device__ __forceinline__ unsigned fenc(float f){
    unsigned b = __float_as_uint(f);
    return (b & 0x80000000u) ? ~b : (b | 0x80000000u);
}
__device__ __forceinline__ float fdec(unsigned u){
    return __uint_as_float((u & 0x80000000u) ? (u & 0x7fffffffu) : ~u);
}
__device__ __forceinline__ float sigm(float x){ return 1.f/(1.f + expf(-x)); }
// quantize 4 consecutive floats -> (hi bytes, lo bytes)
__device__ __forceinline__ uint2 q4(const float* p, float inv){
    uint32_t Hh = 0, Ll = 0;
    #pragma unroll
    for (int b = 0; b < 4; b++){
        int q = __float2int_rn(p[b]*inv);
        int qh = (q + 64) >> 7; int ql = q - (qh << 7);
        Hh |= (uint32_t)(qh & 0xff) << (8*b);
        Ll |= (uint32_t)(ql & 0xff) << (8*b);
    }
    return make_uint2(Hh, Ll);
}

#define MMA16816(d, a, b0_, b1_) \
  asm volatile("mma.sync.aligned.m16n8k16.row.col.f32.bf16.bf16.f32 " \
    "{%0,%1,%2,%3}, {%4,%5,%6,%7}, {%8,%9}, {%0,%1,%2,%3};" \
    : "+f"((d)[0]), "+f"((d)[1]), "+f"((d)[2]), "+f"((d)[3]) \
    : "r"((a)[0]), "r"((a)[1]), "r"((a)[2]), "r"((a)[3]), "r"(b0_), "r"(b1_))

#define IMMA(d, a, b0_, b1_) \
  asm volatile("mma.sync.aligned.m16n8k32.row.col.s32.s8.s8.s32 " \
    "{%0,%1,%2,%3}, {%4,%5,%6,%7}, {%8,%9}, {%0,%1,%2,%3};" \
    : "+r"((d)[0]), "+r"((d)[1]), "+r"((d)[2]), "+r"((d)[3]) \
    : "r"((a)[0]), "r"((a)[1]), "r"((a)[2]), "r"((a)[3]), "r"(b0_), "r"(b1_))

// ---------------- CSR build ----------------
__global__ void csr_zero(){
    int i = blockIdx.x*blockDim.x + threadIdx.x;
    if (i < SEGN) g_deg[i] = 0;
}
__global__ void csr_count(const int* __restrict__ ei, const int* __restrict__ et){
    int e = blockIdx.x*blockDim.x + threadIdx.x;
    if (e >= EE) return;
    int v = c_v_of_t[et[e]];
    atomicAdd(&g_deg[v*NN + ei[EE + e]], 1);
}
__global__ void csr_scan1(){
    __shared__ int sm[1024];
    int t = threadIdx.x, b = blockIdx.x;
    int i = b*1024 + t;
    int v = (i < SEGN) ? g_deg[i] : 0;
    sm[t] = v;
    __syncthreads();
    #pragma unroll
    for (int o = 1; o < 1024; o <<= 1){
        int add = (t >= o) ? sm[t - o] : 0;
        __syncthreads();
        sm[t] += add;
        __syncthreads();
    }
    if (i < SEGN) g_scanT[i] = sm[t];
    if (t == 1023) g_part[b] = sm[1023];
}
__global__ void csr_scan2(){
    __shared__ int sm[SCAN_BLKS];
    int t = threadIdx.x;
    if (t < SCAN_BLKS) sm[t] = g_part[t];
    __syncthreads();
    if (t == 0){
        int run = 0;
        for (int i = 0; i < SCAN_BLKS; i++){ run += sm[i]; g_partS[i] = run; }
    }
}
__global__ void csr_scan3(){
    int i = blockIdx.x*blockDim.x + threadIdx.x;
    if (i >= SEGN) return;
    int b = i >> 10;
    int base = (b > 0) ? g_partS[b-1] : 0;
    int excl = base + g_scanT[i] - g_deg[i];
    g_rowptr[i] = excl;
    g_woff[i]   = excl;
    if (i == 0) g_rowptr[SEGN] = EE;
}
__global__ void csr_fill(const int* __restrict__ ei, const int* __restrict__ et){
    int e = blockIdx.x*blockDim.x + threadIdx.x;
    if (e >= EE) return;
    int v = c_v_of_t[et[e]];
    int pos = atomicAdd(&g_woff[v*NN + ei[EE + e]], 1);
    g_csrsrc[pos] = ei[e];
}

// ---------------- prep: proj/qw/kw^T -> bf16 frags ----------------
__global__ void prep_frags(const float* __restrict__ projw,
                           const float* __restrict__ qw, const float* __restrict__ kw){
    int tid = blockIdx.x*blockDim.x + threadIdx.x;
    if (tid >= FRAG_TOTAL) return;
    const float* M; int rel; bool tr;
    if (tid < OFF_QW){       rel = tid;          M = projw; tr = false; }
    else if (tid < OFF_KWT){ rel = tid-OFF_QW;   M = qw;    tr = false; }
    else{                    rel = tid-OFF_KWT;  M = kw;    tr = true; }
    int lane = rel & 31, t2 = rel >> 5;
    int nt = t2 % 16, kt = t2 / 16;
    int n = nt*8 + (lane >> 2), k0 = kt*16 + (lane & 3)*2;
    float v[4];
    #pragma unroll
    for (int q = 0; q < 4; q++){
        int k = k0 + (q >> 1)*8 + (q & 1);
        v[q] = tr ? M[(size_t)n*128 + k] : M[(size_t)k*128 + n];
    }
    float h[4], l[4];
    #pragma unroll
    for (int q = 0; q < 4; q++){
        h[q] = __bfloat162float(__float2bfloat16(v[q]));
        l[q] = v[q] - h[q];
    }
    uint4 o;
    o.x = packbf(h[0], h[1]); o.y = packbf(h[2], h[3]);
    o.z = packbf(l[0], l[1]); o.w = packbf(l[2], l[3]);
    g_frag[tid] = o;
}

// ---------------- prep: whh -> int8 image + col scales ----------------
__global__ void prep_whh_i8(const float* __restrict__ whh){
    __shared__ float red[4];
    __shared__ float sInv;
    int b = blockIdx.x;            // v*384 + c
    int k = threadIdx.x;           // 0..127
    float val = whh[(size_t)b*128 + k];
    float m = fabsf(val);
    #pragma unroll
    for (int o = 16; o; o >>= 1) m = fmaxf(m, __shfl_xor_sync(0xffffffffu, m, o));
    if ((k & 31) == 0) red[k >> 5] = m;
    __syncthreads();
    if (k == 0){
        float S = fmaxf(fmaxf(red[0], red[1]), fmaxf(red[2], red[3]));
        S = fmaxf(S, 1e-20f);
        g_scU[b] = S * (1.f/16256.f);
        sInv = 16256.f / S;
    }
    __syncthreads();
    int q = __float2int_rn(val * sInv);
    int qh = (q + 64) >> 7, ql = q - (qh << 7);
    int v = b / 384, c = b % 384;
    int kc = k >> 5, kk = k & 31;
    int reg = kk >> 4;
    int lane = (c & 7)*4 + ((kk & 15) >> 2);
    int byi = kk & 3;
    size_t base = ((size_t)v*6144u + (size_t)(kc*48 + (c >> 3))*32 + lane)*16u + reg*4 + byi;
    char* img = (char*)g_imgU;
    img[base]     = (char)qh;
    img[base + 8] = (char)ql;
}

// ---------------- Wcomb = ggnn[v,i] @ wih[v]^T -> int8 image + col scales ------------
__global__ __launch_bounds__(256)
void wcomb_prep(const float* __restrict__ ggnn, const float* __restrict__ wih){
    extern __shared__ float s[];
    float* As = s;
    float* Ws = s + 128*129;
    float* Cs = s + 2*128*129;
    int vi = blockIdx.x, cblk = blockIdx.y, v = vi >> 2;
    const float* A = ggnn + (size_t)vi*16384;
    const float* W = wih + ((size_t)v*H3 + cblk*128)*128;
    int tid = threadIdx.x;
    for (int i = tid; i < 16384; i += 256){
        int r = i >> 7, j = i & 127;
        As[j*129 + r] = A[i];
        Ws[j*129 + r] = W[i];
    }
    __syncthreads();
    int tx = tid & 15, ty = tid >> 4;
    float acc[8][8];
    #pragma unroll
    for (int a = 0; a < 8; a++)
        #pragma unroll
        for (int b = 0; b < 8; b++) acc[a][b] = 0.f;
    for (int j = 0; j < 128; j++){
        float av[8], wv[8];
        #pragma unroll
        for (int q = 0; q < 8; q++){
            av[q] = As[j*129 + ty*8 + q];
            wv[q] = Ws[j*129 + tx*8 + q];
        }
        #pragma unroll
        for (int a = 0; a < 8; a++)
            #pragma unroll
            for (int b = 0; b < 8; b++) acc[a][b] += av[a]*wv[b];
    }
    #pragma unroll
    for (int a = 0; a < 8; a++)
        #pragma unroll
        for (int b = 0; b < 8; b++)
            Cs[(ty*8+a)*128 + tx*8+b] = acc[a][b];
    __syncthreads();
    if (tid < 128){
        float m = 0.f;
        for (int k = 0; k < 128; k++) m = fmaxf(m, fabsf(Cs[k*128 + tid]));
        m = fmaxf(m, 1e-20f);
        g_scW[vi*384 + cblk*128 + tid] = m * (1.f/16256.f);
        As[tid] = 16256.f / m;
    }
    __syncthreads();
    for (int it = tid; it < 2048; it += 256){
        int lane = it & 31, t2 = it >> 5;
        int lnt = t2 & 15, kc = t2 >> 4;
        int c = lnt*8 + (lane >> 2);
        float inv = As[c];
        int k0 = kc*32 + (lane & 3)*4;
        uint32_t H0=0,H1=0,L0=0,L1=0;
        #pragma unroll
        for (int b = 0; b < 4; b++){
            int q = __float2int_rn(Cs[(k0+b)*128 + c] * inv);
            int qh = (q+64)>>7, ql = q-(qh<<7);
            H0 |= (uint32_t)(qh & 0xff) << (8*b);
            L0 |= (uint32_t)(ql & 0xff) << (8*b);
            q = __float2int_rn(Cs[(k0+16+b)*128 + c] * inv);
            qh = (q+64)>>7; ql = q-(qh<<7);
            H1 |= (uint32_t)(qh & 0xff) << (8*b);
            L1 |= (uint32_t)(ql & 0xff) << (8*b);
        }
        g_imgW[(size_t)vi*6144u + (size_t)(kc*48 + cblk*16 + lnt)*32 + lane] = make_uint4(H0,H1,L0,L1);
    }
}

// ---------------- HMMA GEMM (proj / q / qk) ----------------
__global__ __launch_bounds__(256)
void gemm_mma(const float* __restrict__ A, int lda, int M,
              const uint4* __restrict__ frag, int NT, int KT,
              const float* __restrict__ bias, float* __restrict__ C,
              int ldc, int act){
    int tid = threadIdx.x, wid = tid >> 5, lane = tid & 31;
    int wm = wid >> 1, wn = wid & 1;
    int gid = lane >> 2, tig = lane & 3;
    int rowBase = blockIdx.x*128 + wm*32 + gid;
    int ntG0 = blockIdx.y*16 + wn*8;

    float acc[2][8][4];
    #pragma unroll
    for (int mt = 0; mt < 2; mt++)
        #pragma unroll
        for (int nt = 0; nt < 8; nt++)
            #pragma unroll
            for (int q = 0; q < 4; q++) acc[mt][nt][q] = 0.f;

    float2 ax[2][4];
    auto loadA = [&](int kt){
        #pragma unroll
        for (int mt = 0; mt < 2; mt++){
            int r = rowBase + mt*16;
            int k = kt*16 + tig*2;
            bool p0 = (r < M), p1 = (r + 8 < M);
            const float* base0 = A + (size_t)r*lda + k;
            const float* base1 = A + (size_t)(r+8)*lda + k;
            ax[mt][0] = p0 ? *(const float2*)(base0)     : make_float2(0.f, 0.f);
            ax[mt][1] = p1 ? *(const float2*)(base1)     : make_float2(0.f, 0.f);
            ax[mt][2] = p0 ? *(const float2*)(base0 + 8) : make_float2(0.f, 0.f);
            ax[mt][3] = p1 ? *(const float2*)(base1 + 8) : make_float2(0.f, 0.f);
        }
    };
    loadA(0);
    uint4 bcur = frag[((size_t)(0*NT + ntG0))*32 + lane];

    for (int kt = 0; kt < KT; kt++){
        uint32_t Ah[2][4], Al[2][4];
        #pragma unroll
        for (int mt = 0; mt < 2; mt++){
            #pragma unroll
            for (int q = 0; q < 4; q++){
                float2 vv = ax[mt][q];
                float hx = __bfloat162float(__float2bfloat16(vv.x));
                float hy = __bfloat162float(__float2bfloat16(vv.y));
                Ah[mt][q] = packbf(vv.x, vv.y);
                Al[mt][q] = packbf(vv.x - hx, vv.y - hy);
            }
        }
        if (kt + 1 < KT) loadA(kt + 1);
        #pragma unroll
        for (int nt = 0; nt < 8; nt++){
            uint4 bn;
            if (nt < 7)           bn = frag[((size_t)(kt*NT + ntG0 + nt + 1))*32 + lane];
            else if (kt + 1 < KT) bn = frag[((size_t)((kt+1)*NT + ntG0))*32 + lane];
            else                  bn = bcur;
            #pragma unroll
            for (int mt = 0; mt < 2; mt++){
                MMA16816(acc[mt][nt], Ah[mt], bcur.x, bcur.y);
                MMA16816(acc[mt][nt], Ah[mt], bcur.z, bcur.w);
                MMA16816(acc[mt][nt], Al[mt], bcur.x, bcur.y);
            }
            bcur = bn;
        }
    }

    #pragma unroll
    for (int nt = 0; nt < 8; nt++){
        int col = (ntG0 + nt)*8 + tig*2;
        float b0 = 0.f, b1 = 0.f;
        if (bias){ b0 = bias[col]; b1 = bias[col + 1]; }
        #pragma unroll
        for (int mt = 0; mt < 2; mt++){
            int r = rowBase + mt*16;
            float v0 = acc[mt][nt][0] + b0, v1 = acc[mt][nt][1] + b1;
            float v2 = acc[mt][nt][2] + b0, v3 = acc[mt][nt][3] + b1;
            if (act == 1){ v0 = tanhf(v0); v1 = tanhf(v1); v2 = tanhf(v2); v3 = tanhf(v3); }
            if (r < M)     *(float2*)(C + (size_t)r*ldc + col)     = make_float2(v0, v1);
            if (r + 8 < M) *(float2*)(C + (size_t)(r+8)*ldc + col) = make_float2(v2, v3);
        }
    }
}

// ---------------- fused GRU cell v6: int8 IMMA k32, 2x fewer tensor instrs ------------
// 8 warps = 4 gates x 2 col-slices (64 cols, nt in 2 halves of 4).
#define GPASS_I8(QH, QL, IMG, RS, CS, GATE, FIRST) do { \
  for (int half = 0; half < 2; half++){ \
    int accH[2][4][4], accX[2][4][4]; \
    _Pragma("unroll") for (int a1 = 0; a1 < 2; a1++) \
    _Pragma("unroll") for (int a2 = 0; a2 < 4; a2++) \
    _Pragma("unroll") for (int a3 = 0; a3 < 4; a3++){ accH[a1][a2][a3] = 0; accX[a1][a2][a3] = 0; } \
    _Pragma("unroll 1") \
    for (int kc = 0; kc < 4; kc++){ \
      uint4 fh0 = (QH)[kc*32 + lane],       fl0 = (QL)[kc*32 + lane]; \
      uint4 fh1 = (QH)[128 + kc*32 + lane], fl1 = (QL)[128 + kc*32 + lane]; \
      uint32_t AH0[4] = {fh0.x, fh0.y, fh0.z, fh0.w}; \
      uint32_t AL0[4] = {fl0.x, fl0.y, fl0.z, fl0.w}; \
      uint32_t AH1[4] = {fh1.x, fh1.y, fh1.z, fh1.w}; \
      uint32_t AL1[4] = {fl1.x, fl1.y, fl1.z, fl1.w}; \
      _Pragma("unroll") \
      for (int nt = 0; nt < 4; nt++){ \
        uint4 b = (IMG)[(size_t)kc*1536 + (size_t)((GATE)*16 + sub*8 + half*4 + nt)*32 + lane]; \
        IMMA(accH[0][nt], AH0, b.x, b.y); \
        IMMA(accX[0][nt], AH0, b.z, b.w); \
        IMMA(accX[0][nt], AL0, b.x, b.y); \
        IMMA(accH[1][nt], AH1, b.x, b.y); \
        IMMA(accX[1][nt], AH1, b.z, b.w); \
        IMMA(accX[1][nt], AL1, b.x, b.y); \
      } \
    } \
    _Pragma("unroll") \
    for (int mt = 0; mt < 2; mt++){ \
      int r0 = mt*16 + gid; \
      float rs0 = (RS)[r0], rs1 = (RS)[r0 + 8]; \
      _Pragma("unroll") \
      for (int nt = 0; nt < 4; nt++){ \
        int colg = sub*64 + half*32 + nt*8 + tig*2; \
        float cs0 = (CS)[(GATE)*128 + colg], cs1 = (CS)[(GATE)*128 + colg + 1]; \
        float v00 = ((float)accH[mt][nt][0]*16384.f + (float)accX[mt][nt][0]*128.f)*rs0*cs0; \
        float v01 = ((float)accH[mt][nt][1]*16384.f + (float)accX[mt][nt][1]*128.f)*rs0*cs1; \
        float v10 = ((float)accH[mt][nt][2]*16384.f + (float)accX[mt][nt][2]*128.f)*rs1*cs0; \
        float v11 = ((float)accH[mt][nt][3]*16384.f + (float)accX[mt][nt][3]*128.f)*rs1*cs1; \
        float* p0 = gb + r0*128 + colg; \
        float* p1 = gb + (r0+8)*128 + colg; \
        if (FIRST){ \
            *(float2*)p0 = make_float2(v00, v01); \
            *(float2*)p1 = make_float2(v10, v11); \
        } else { \
            float2 o0 = *(float2*)p0, o1 = *(float2*)p1; \
            *(float2*)p0 = make_float2(o0.x + v00, o0.y + v01); \
            *(float2*)p1 = make_float2(o1.x + v10, o1.y + v11); \
        } \
      } \
    } \
  } } while(0)

__global__ __launch_bounds__(256, 2)
void gru_fused(const float* __restrict__ Hin, float* __restrict__ Hout,
               const uint4* __restrict__ imgW, const uint4* __restrict__ imgU,
               const float* __restrict__ scW, const float* __restrict__ scU,
               const float* __restrict__ bih, const float* __restrict__ bhh,
               const int* __restrict__ rowptrB, size_t hinStride){
    extern __shared__ char sm[];
    uint4* sQGh  = (uint4*)sm;                 // 4KB each
    uint4* sQGl  = (uint4*)(sm + 4096);
    uint4* sQHh  = (uint4*)(sm + 8192);
    uint4* sQHl  = (uint4*)(sm + 12288);
    float* sHval = (float*)(sm + 16384);       // 16KB live
    float* sAval = (float*)(sm + 32768);       // 16KB -> gate r after pack
    float* sGz   = (float*)(sm + 49152);
    float* sGi   = (float*)(sm + 65536);
    float* sGn   = (float*)(sm + 81920);
    float* sbias = (float*)(sm + 98304);       // 512 f
    float* sCW   = (float*)(sm + 100352);      // 384
    float* sCU   = (float*)(sm + 101888);      // 384
    float* sSG   = (float*)(sm + 103424);      // 32
    float* sSH   = (float*)(sm + 103552);
    float* sIG   = (float*)(sm + 103680);
    float* sIH   = (float*)(sm + 103808);
    float* sGr   = sAval;
    int tid = threadIdx.x, wid = tid >> 5, lane = tid & 31;
    int gid = lane >> 2, tig = lane & 3;

    int v   = blockIdx.x / GRU_GRID;
    int blk = blockIdx.x % GRU_GRID;
    int m0 = blk*32;
    const float* Hsrc = Hin + (size_t)v * hinStride;
    Hout += (size_t)v * NN * HH;
    imgW += (size_t)v * 24576u;
    imgU += (size_t)v * 6144u;
    scW  += v * 1536;
    scU  += v * 384;
    bih  += v * H3;
    bhh  += v * H3;
    const int* rowptr = rowptrB + v * NN;

    if (tid < 128){
        sbias[tid]     = bih[tid]     + bhh[tid];
        sbias[128+tid] = bih[128+tid] + bhh[128+tid];
        sbias[256+tid] = bih[256+tid];
        sbias[384+tid] = bhh[256+tid];
    }
    for (int i = tid; i < 384; i += 256){ sCW[i] = scW[i]; sCU[i] = scU[i]; }

    for (int it = tid; it < 32*32; it += 256){
        int r = it >> 5, c4 = it & 31;
        float4 hv = make_float4(0.f,0.f,0.f,0.f);
        if (m0 + r < NN) hv = *(const float4*)(Hsrc + (size_t)(m0+r)*HH + c4*4);
        *(float4*)(sHval + r*128 + c4*4) = hv;
    }
    for (int rr = wid; rr < 32; rr += 8){
        int grow = m0 + rr;
        float4 acc = make_float4(0.f,0.f,0.f,0.f);
        if (grow < NN){
            int s = rowptr[grow], e = rowptr[grow + 1];
            int idx = s;
            while (idx + 4 <= e){
                int a0 = g_csrsrc[idx], a1 = g_csrsrc[idx+1];
                int a2 = g_csrsrc[idx+2], a3 = g_csrsrc[idx+3];
                float4 v0 = *(const float4*)(Hsrc + (size_t)a0*HH + lane*4);
                float4 v1 = *(const float4*)(Hsrc + (size_t)a1*HH + lane*4);
                float4 v2 = *(const float4*)(Hsrc + (size_t)a2*HH + lane*4);
                float4 v3 = *(const float4*)(Hsrc + (size_t)a3*HH + lane*4);
                acc.x += v0.x + v1.x + v2.x + v3.x;
                acc.y += v0.y + v1.y + v2.y + v3.y;
                acc.z += v0.z + v1.z + v2.z + v3.z;
                acc.w += v0.w + v1.w + v2.w + v3.w;
                idx += 4;
            }
            while (idx < e){
                int a0 = g_csrsrc[idx];
                float4 v0 = *(const float4*)(Hsrc + (size_t)a0*HH + lane*4);
                acc.x += v0.x; acc.y += v0.y; acc.z += v0.z; acc.w += v0.w;
                idx++;
            }
        }
        *(float4*)(sAval + rr*128 + lane*4) = acc;
    }
    __syncthreads();

    // per-row scales (64 rows: 0-31 G, 32-63 h); 4 threads per row
    {
        int r8 = tid >> 2, sl = tid & 3;
        const float* src = (r8 < 32) ? (sAval + r8*128) : (sHval + (r8-32)*128);
        float m = 0.f;
        for (int k = sl*4; k < 128; k += 16){
            float4 vv = *(const float4*)(src + k);
            m = fmaxf(m, fmaxf(fmaxf(fabsf(vv.x), fabsf(vv.y)), fmaxf(fabsf(vv.z), fabsf(vv.w))));
        }
        m = fmaxf(m, __shfl_xor_sync(0xffffffffu, m, 1));
        m = fmaxf(m, __shfl_xor_sync(0xffffffffu, m, 2));
        if (sl == 0){
            m = fmaxf(m, 1e-20f);
            if (r8 < 32){ sSG[r8] = m*(1.f/16256.f); sIG[r8] = 16256.f/m; }
            else        { sSH[r8-32] = m*(1.f/16256.f); sIH[r8-32] = 16256.f/m; }
        }
    }
    __syncthreads();

    // pack int8 A fragments (one item per thread: mt,kc,lane)
    {
        int mt = tid >> 7, kc = (tid >> 5) & 3, ln = tid & 31;
        int row = mt*16 + (ln >> 2);
        int k0 = kc*32 + (ln & 3)*4;
        uint2 a0 = q4(sAval + row*128 + k0,        sIG[row]);
        uint2 a1 = q4(sAval + (row+8)*128 + k0,    sIG[row+8]);
        uint2 a2 = q4(sAval + row*128 + k0+16,     sIG[row]);
        uint2 a3 = q4(sAval + (row+8)*128 + k0+16, sIG[row+8]);
        sQGh[mt*128 + kc*32 + ln] = make_uint4(a0.x, a1.x, a2.x, a3.x);
        sQGl[mt*128 + kc*32 + ln] = make_uint4(a0.y, a1.y, a2.y, a3.y);
        uint2 b0 = q4(sHval + row*128 + k0,        sIH[row]);
        uint2 b1 = q4(sHval + (row+8)*128 + k0,    sIH[row+8]);
        uint2 b2 = q4(sHval + row*128 + k0+16,     sIH[row]);
        uint2 b3 = q4(sHval + (row+8)*128 + k0+16, sIH[row+8]);
        sQHh[mt*128 + kc*32 + ln] = make_uint4(b0.x, b1.x, b2.x, b3.x);
        sQHl[mt*128 + kc*32 + ln] = make_uint4(b0.y, b1.y, b2.y, b3.y);
    }
    __syncthreads();

    int g = wid >> 1, sub = wid & 1;
    float* gb = (g == 0) ? sGr : (g == 1) ? sGz : (g == 2) ? sGi : sGn;
    if (g == 0){
        GPASS_I8(sQGh, sQGl, imgW, sSG, sCW, 0, true);
        GPASS_I8(sQHh, sQHl, imgU, sSH, sCU, 0, false);
    } else if (g == 1){
        GPASS_I8(sQGh, sQGl, imgW, sSG, sCW, 1, true);
        GPASS_I8(sQHh, sQHl, imgU, sSH, sCU, 1, false);
    } else if (g == 2){
        GPASS_I8(sQGh, sQGl, imgW, sSG, sCW, 2, true);
    } else {
        GPASS_I8(sQHh, sQHl, imgU, sSH, sCU, 2, true);
    }
    __syncthreads();

    // epilogue: warp per row (4 rows/warp), lane = 4 cols
    for (int rr = wid; rr < 32; rr += 8){
        int grow = m0 + rr;
        if (grow >= NN) continue;
        int col = lane*4;
        float4 r4 = *(float4*)(sGr + rr*128 + col);
        float4 z4 = *(float4*)(sGz + rr*128 + col);
        float4 i4 = *(float4*)(sGi + rr*128 + col);
        float4 n4 = *(float4*)(sGn + rr*128 + col);
        float4 h4 = *(float4*)(sHval + rr*128 + col);
        float4 br = *(float4*)(sbias + col);
        float4 bz = *(float4*)(sbias + 128 + col);
        float4 bi = *(float4*)(sbias + 256 + col);
        float4 bh = *(float4*)(sbias + 384 + col);
        float4 o;
        {
            float r_ = sigm(r4.x + br.x), z_ = sigm(z4.x + bz.x);
            float n_ = tanhf(i4.x + bi.x + r_*(n4.x + bh.x));
            o.x = (1.f - z_)*n_ + z_*h4.x;
        }
        {
            float r_ = sigm(r4.y + br.y), z_ = sigm(z4.y + bz.y);
            float n_ = tanhf(i4.y + bi.y + r_*(n4.y + bh.y));
            o.y = (1.f - z_)*n_ + z_*h4.y;
        }
        {
            float r_ = sigm(r4.z + br.z), z_ = sigm(z4.z + bz.z);
            float n_ = tanhf(i4.z + bi.z + r_*(n4.z + bh.z));
            o.z = (1.f - z_)*n_ + z_*h4.z;
        }
        {
            float r_ = sigm(r4.w + br.w), z_ = sigm(z4.w + bz.w);
            float n_ = tanhf(i4.w + bi.w + r_*(n4.w + bh.w));
            o.w = (1.f - z_)*n_ + z_*h4.w;
        }
        *(float4*)(Hout + (size_t)grow*HH + col) = o;
    }
}

// ---------------- LN + GELU after projection ----------------
__global__ void ln_gelu(const float* __restrict__ lnw, const float* __restrict__ lnb){
    int gw = (blockIdx.x*blockDim.x + threadIdx.x) >> 5;
    if (gw >= NN) return;
    int lane = threadIdx.x & 31;
    float xv[4], s = 0.f, s2 = 0.f;
    #pragma unroll
    for (int i = 0; i < 4; i++){
        xv[i] = g_proj[(size_t)gw*HH + lane + 32*i];
        s += xv[i]; s2 += xv[i]*xv[i];
    }
    #pragma unroll
    for (int o = 16; o; o >>= 1){
        s  += __shfl_xor_sync(0xffffffffu, s,  o);
        s2 += __shfl_xor_sync(0xffffffffu, s2, o);
    }
    float mu = s*(1.f/HH), var = s2*(1.f/HH) - mu*mu;
    float rstd = rsqrtf(var + 1e-5f);
    #pragma unroll
    for (int i = 0; i < 4; i++){
        int j = lane + 32*i;
        float y = (xv[i] - mu)*rstd*lnw[j] + lnb[j];
        g_h0[(size_t)gw*HH + j] = 0.5f*y*(1.f + erff(y*0.7071067811865476f));
    }
}

// ---------------- fused LN + residual + attention ----------------
__global__ void ln_attn(const float* __restrict__ hall,
                        const float* __restrict__ vlnw, const float* __restrict__ vlnb){
    int gw = (blockIdx.x*blockDim.x + threadIdx.x) >> 5;
    if (gw >= NN) return;
    int lane = threadIdx.x & 31;
    float h0v[4], qkv[4];
    #pragma unroll
    for (int i = 0; i < 4; i++){
        h0v[i] = g_h0[(size_t)gw*HH + lane + 32*i];
        qkv[i] = g_qk[(size_t)gw*HH + lane + 32*i];
    }
    float y[4][4], sc[4];
    #pragma unroll
    for (int v = 0; v < 4; v++){
        float xv[4], s = 0.f, s2 = 0.f;
        #pragma unroll
        for (int i = 0; i < 4; i++){
            xv[i] = hall[((size_t)v*NN + gw)*HH + lane + 32*i];
            s += xv[i]; s2 += xv[i]*xv[i];
        }
        #pragma unroll
        for (int o = 16; o; o >>= 1){
            s  += __shfl_xor_sync(0xffffffffu, s,  o);
            s2 += __shfl_xor_sync(0xffffffffu, s2, o);
        }
        float mu = s*(1.f/HH), var = s2*(1.f/HH) - mu*mu;
        float rstd = rsqrtf(var + 1e-5f);
        float p = 0.f;
        #pragma unroll
        for (int i = 0; i < 4; i++){
            int j = lane + 32*i;
            y[v][i] = (xv[i] - mu)*rstd*vlnw[v*HH + j] + vlnb[v*HH + j] + h0v[i];
            p += qkv[i]*y[v][i];
        }
        #pragma unroll
        for (int o = 16; o; o >>= 1) p += __shfl_xor_sync(0xffffffffu, p, o);
        sc[v] = p * 0.08838834764831845f;
    }
    float mx = fmaxf(fmaxf(sc[0], sc[1]), fmaxf(sc[2], sc[3]));
    float ex[4], sum = 0.f;
    #pragma unroll
    for (int v = 0; v < 4; v++){ ex[v] = expf(sc[v] - mx); sum += ex[v]; }
    float inv = 1.f/sum;
    #pragma unroll
    for (int i = 0; i < 4; i++){
        float o = 0.f;
        #pragma unroll
        for (int v = 0; v < 4; v++) o += ex[v]*inv*y[v][i];
        g_fused[(size_t)gw*HH + lane + 32*i] = o;
    }
}

// ---------------- pooling ----------------
__global__ void pool_init(){
    int i = blockIdx.x*blockDim.x + threadIdx.x;
    if (i < BB*HH){ g_psum[i] = 0.f; g_pmax[i] = 0u; }
    if (i < BB) g_cnt[i] = 0.f;
}
__global__ void pool_acc(const int* __restrict__ batch){
    int j = threadIdx.x;
    int n0 = blockIdx.x * 64;
    int cur = -1; float sum = 0.f, mx = -1e30f; int cnt = 0;
    for (int t = 0; t < 64; t++){
        int n = n0 + t;
        if (n >= NN) break;
        int b = batch[n];
        if (b != cur){
            if (cur >= 0){
                atomicAdd(&g_psum[cur*HH + j], sum);
                atomicMax(&g_pmax[cur*HH + j], fenc(mx));
                if (j == 0) atomicAdd(&g_cnt[cur], (float)cnt);
            }
            cur = b; sum = 0.f; mx = -1e30f; cnt = 0;
        }
        float f = g_fused[(size_t)n*HH + j];
        sum += f; mx = fmaxf(mx, f); cnt++;
    }
    if (cur >= 0){
        atomicAdd(&g_psum[cur*HH + j], sum);
        atomicMax(&g_pmax[cur*HH + j], fenc(mx));
        if (j == 0) atomicAdd(&g_cnt[cur], (float)cnt);
    }
}

// ---------------- classifier ----------------
__global__ void classifier(const float* __restrict__ c1w, const float* __restrict__ c1b,
                           const float* __restrict__ c2w, const float* __restrict__ c2b,
                           const float* __restrict__ c3w, const float* __restrict__ c3b,
                           float* __restrict__ out){
    __shared__ float gsh[2*HH], h1[HH], h2[64];
    int b = blockIdx.x, j = threadIdx.x;
    float cnt = fmaxf(g_cnt[b], 1.f);
    gsh[j]      = g_psum[b*HH + j] / cnt;
    gsh[HH + j] = fdec(g_pmax[b*HH + j]);
    __syncthreads();
    float a = c1b[j];
    for (int k = 0; k < 2*HH; k++) a += gsh[k]*c1w[k*HH + j];
    h1[j] = fmaxf(a, 0.f);
    __syncthreads();
    if (j < 64){
        float a2 = c2b[j];
        for (int k = 0; k < HH; k++) a2 += h1[k]*c2w[k*64 + j];
        h2[j] = fmaxf(a2, 0.f);
    }
    __syncthreads();
    if (j == 0){
        float o = c3b[0];
        for (int k = 0; k < 64; k++) o += h2[k]*c3w[k];
        out[b] = o;
    }
}

// ---------------- launch ----------------
extern "C" void kernel_launch(void* const* d_in, const int* in_sizes, int n_in,
                              void* d_out, int out_size){
    (void)in_sizes; (void)n_in; (void)out_size;
    const float* x      = (const float*)d_in[0];
    const int*   ei     = (const int*)  d_in[1];
    const int*   et     = (const int*)  d_in[2];
    const int*   batch  = (const int*)  d_in[3];
    const float* proj_w = (const float*)d_in[4];
    const float* proj_b = (const float*)d_in[5];
    const float* ln0w   = (const float*)d_in[6];
    const float* ln0b   = (const float*)d_in[7];
    const float* ggnn   = (const float*)d_in[8];
    const float* wih    = (const float*)d_in[9];
    const float* whh    = (const float*)d_in[10];
    const float* bih    = (const float*)d_in[11];
    const float* bhh    = (const float*)d_in[12];
    const float* vlnw   = (const float*)d_in[13];
    const float* vlnb   = (const float*)d_in[14];
    const float* qw     = (const float*)d_in[15];
    const float* qb     = (const float*)d_in[16];
    const float* kw     = (const float*)d_in[17];
    const float* c1w    = (const float*)d_in[19];
    const float* c1b    = (const float*)d_in[20];
    const float* c2w    = (const float*)d_in[21];
    const float* c2b    = (const float*)d_in[22];
    const float* c3w    = (const float*)d_in[23];
    const float* c3b    = (const float*)d_in[24];
    float* out = (float*)d_out;

    float *p_h0, *p_hallA, *p_hallB, *p_proj, *p_q, *p_qk, *p_scW, *p_scU;
    uint4 *p_frag, *p_imgW, *p_imgU;
    int* p_rowptr;
    cudaGetSymbolAddress((void**)&p_h0,    g_h0);
    cudaGetSymbolAddress((void**)&p_hallA, g_hallA);
    cudaGetSymbolAddress((void**)&p_hallB, g_hallB);
    cudaGetSymbolAddress((void**)&p_proj,  g_proj);
    cudaGetSymbolAddress((void**)&p_q,     g_q);
    cudaGetSymbolAddress((void**)&p_qk,    g_qk);
    cudaGetSymbolAddress((void**)&p_frag,  g_frag);
    cudaGetSymbolAddress((void**)&p_imgW,  g_imgW);
    cudaGetSymbolAddress((void**)&p_imgU,  g_imgU);
    cudaGetSymbolAddress((void**)&p_scW,   g_scW);
    cudaGetSymbolAddress((void**)&p_scU,   g_scU);
    cudaGetSymbolAddress((void**)&p_rowptr, g_rowptr);

    const int GRU_SMEM = 103936;   // ~101.5KB -> 2 CTAs/SM
    cudaFuncSetAttribute(gru_fused, cudaFuncAttributeMaxDynamicSharedMemorySize, GRU_SMEM);
    const int WC_SMEM = (2*128*129 + 128*128) * 4;
    cudaFuncSetAttribute(wcomb_prep, cudaFuncAttributeMaxDynamicSharedMemorySize, WC_SMEM);

    const size_t NH = (size_t)NN*HH;

    csr_zero<<<(SEGN + 255)/256, 256>>>();
    csr_count<<<(EE + 255)/256, 256>>>(ei, et);
    csr_scan1<<<SCAN_BLKS, 1024>>>();
    csr_scan2<<<1, 1024>>>();
    csr_scan3<<<(SEGN + 255)/256, 256>>>();
    csr_fill<<<(EE + 255)/256, 256>>>(ei, et);

    prep_frags<<<(FRAG_TOTAL + 255)/256, 256>>>(proj_w, qw, kw);
    prep_whh_i8<<<1536, 128>>>(whh);
    wcomb_prep<<<dim3(16,3), 256, WC_SMEM>>>(ggnn, wih);

    gemm_mma<<<dim3(MT,1), 256>>>(x, INF_, NN, p_frag + OFF_PROJ, 16, 32, proj_b, p_proj, HH, 0);
    ln_gelu<<<(NN*32 + 255)/256, 256>>>(ln0w, ln0b);

    gemm_mma<<<dim3(MT,1), 256>>>(p_h0, HH, NN, p_frag + OFF_QW, 16, 8, qb, p_q, HH, 1);
    gemm_mma<<<dim3(MT,1), 256>>>(p_q, HH, NN, p_frag + OFF_KWT, 16, 8, nullptr, p_qk, HH, 0);

    float* bufs[2] = { p_hallA, p_hallB };
    const float* hin = p_h0;
    size_t hinStride = 0;
    float* hout = p_hallA;
    for (int i = 0; i < 4; i++){
        gru_fused<<<4*GRU_GRID, 256, GRU_SMEM>>>(hin, hout,
            p_imgW + (size_t)i*6144, p_imgU,
            p_scW + i*384, p_scU,
            bih, bhh, p_rowptr, hinStride);
        hin = hout;
        hinStride = NH;
        hout = bufs[(i + 1) & 1];
    }
    const float* hfinal = hin;

    ln_attn<<<(NN*32 + 255)/256, 256>>>(hfinal, vlnw, vlnb);

    pool_init<<<(BB*HH + 255)/256, 256>>>();
    pool_acc<<<(NN + 63)/64, 128>>>(batch);
    classifier<<<BB, 128>>>(c1w, c1b, c2w, c2b, c3w, c3b, out);
}

// round 16
// speedup vs baseline: 2.1432x; 2.1432x over previous
#include <cuda_runtime.h>
#include <cuda_bf16.h>
#include <cuda_fp16.h>
#include <cstdint>
#include <math.h>

#define NN   50000
#define EE   600000
#define INF_ 512
#define HH   128
#define H3   384
#define BB   64
#define MT   ((NN + 127) / 128)
#define SEGN (4*NN)
#define SCAN_BLKS ((SEGN + 1023)/1024)
#define GRU_GRID ((NN + 31)/32)

// ---------------- device scratch ----------------
__device__ float g_h0   [(size_t)NN*HH];
__device__ float g_hallA[(size_t)4*NN*HH];
__device__ float g_hallB[(size_t)4*NN*HH];
__device__ float g_proj [(size_t)NN*HH];
__device__ float g_q    [(size_t)NN*HH];
__device__ float g_qk   [(size_t)NN*HH];
__device__ float g_fused[(size_t)NN*HH];
__device__ float g_psum[BB*HH];
__device__ unsigned g_pmax[BB*HH];
__device__ float g_cnt [BB];

__device__ int g_deg   [SEGN];
__device__ int g_scanT [SEGN];
__device__ int g_part  [SCAN_BLKS];
__device__ int g_partS [SCAN_BLKS];
__device__ int g_rowptr[SEGN + 1];
__device__ int g_woff  [SEGN];
__device__ int g_csrsrc[EE];

// bf16 hi/lo frags for proj/q/qk (exact path)
#define OFF_PROJ 0
#define OFF_QW   16384
#define OFF_KWT  20480
#define FRAG_TOTAL 24576
__device__ uint4 g_frag[FRAG_TOTAL];

// fp16 single-pass frags for GRU weights: per matrix 8kt x 48nt x 32lane uint2 = 12288
__device__ uint2 g_imgW[16u*12288u];   // Wcomb[v][i]
__device__ uint2 g_imgU[ 4u*12288u];   // Whh[v]

__constant__ int c_v_of_t[13] = {0,1,1,1,2,2,2,3,3,0,0,3,3};

// ---------------- helpers ----------------
__device__ __forceinline__ uint32_t packbf(float a, float b){
    __nv_bfloat162 t = __halves2bfloat162(__float2bfloat16(a), __float2bfloat16(b));
    return *reinterpret_cast<uint32_t*>(&t);
}
__device__ __forceinline__ uint32_t packh(float a, float b){
    __half2 t = __floats2half2_rn(a, b);
    return *reinterpret_cast<uint32_t*>(&t);
}
__device__ __forceinline__ unsigned fenc(float f){
    unsigned b = __float_as_uint(f);
    return (b & 0x80000000u) ? ~b : (b | 0x80000000u);
}
__device__ __forceinline__ float fdec(unsigned u){
    return __uint_as_float((u & 0x80000000u) ? (u & 0x7fffffffu) : ~u);
}
__device__ __forceinline__ float sigm(float x){ return 1.f/(1.f + expf(-x)); }

#define MMA16816(d, a, b0_, b1_) \
  asm volatile("mma.sync.aligned.m16n8k16.row.col.f32.bf16.bf16.f32 " \
    "{%0,%1,%2,%3}, {%4,%5,%6,%7}, {%8,%9}, {%0,%1,%2,%3};" \
    : "+f"((d)[0]), "+f"((d)[1]), "+f"((d)[2]), "+f"((d)[3]) \
    : "r"((a)[0]), "r"((a)[1]), "r"((a)[2]), "r"((a)[3]), "r"(b0_), "r"(b1_))

#define MMAF16(d, a, b0_, b1_) \
  asm volatile("mma.sync.aligned.m16n8k16.row.col.f32.f16.f16.f32 " \
    "{%0,%1,%2,%3}, {%4,%5,%6,%7}, {%8,%9}, {%0,%1,%2,%3};" \
    : "+f"((d)[0]), "+f"((d)[1]), "+f"((d)[2]), "+f"((d)[3]) \
    : "r"((a)[0]), "r"((a)[1]), "r"((a)[2]), "r"((a)[3]), "r"(b0_), "r"(b1_))

// ---------------- CSR build ----------------
__global__ void csr_zero(){
    int i = blockIdx.x*blockDim.x + threadIdx.x;
    if (i < SEGN) g_deg[i] = 0;
}
__global__ void csr_count(const int* __restrict__ ei, const int* __restrict__ et){
    int e = blockIdx.x*blockDim.x + threadIdx.x;
    if (e >= EE) return;
    int v = c_v_of_t[et[e]];
    atomicAdd(&g_deg[v*NN + ei[EE + e]], 1);
}
__global__ void csr_scan1(){
    __shared__ int sm[1024];
    int t = threadIdx.x, b = blockIdx.x;
    int i = b*1024 + t;
    int v = (i < SEGN) ? g_deg[i] : 0;
    sm[t] = v;
    __syncthreads();
    #pragma unroll
    for (int o = 1; o < 1024; o <<= 1){
        int add = (t >= o) ? sm[t - o] : 0;
        __syncthreads();
        sm[t] += add;
        __syncthreads();
    }
    if (i < SEGN) g_scanT[i] = sm[t];
    if (t == 1023) g_part[b] = sm[1023];
}
__global__ void csr_scan2(){
    __shared__ int sm[SCAN_BLKS];
    int t = threadIdx.x;
    if (t < SCAN_BLKS) sm[t] = g_part[t];
    __syncthreads();
    if (t == 0){
        int run = 0;
        for (int i = 0; i < SCAN_BLKS; i++){ run += sm[i]; g_partS[i] = run; }
    }
}
__global__ void csr_scan3(){
    int i = blockIdx.x*blockDim.x + threadIdx.x;
    if (i >= SEGN) return;
    int b = i >> 10;
    int base = (b > 0) ? g_partS[b-1] : 0;
    int excl = base + g_scanT[i] - g_deg[i];
    g_rowptr[i] = excl;
    g_woff[i]   = excl;
    if (i == 0) g_rowptr[SEGN] = EE;
}
__global__ void csr_fill(const int* __restrict__ ei, const int* __restrict__ et){
    int e = blockIdx.x*blockDim.x + threadIdx.x;
    if (e >= EE) return;
    int v = c_v_of_t[et[e]];
    int pos = atomicAdd(&g_woff[v*NN + ei[EE + e]], 1);
    g_csrsrc[pos] = ei[e];
}

// ---------------- prep: proj/qw/kw^T -> bf16 hi/lo frags ----------------
__global__ void prep_frags(const float* __restrict__ projw,
                           const float* __restrict__ qw, const float* __restrict__ kw){
    int tid = blockIdx.x*blockDim.x + threadIdx.x;
    if (tid >= FRAG_TOTAL) return;
    const float* M; int rel; bool tr;
    if (tid < OFF_QW){       rel = tid;          M = projw; tr = false; }
    else if (tid < OFF_KWT){ rel = tid-OFF_QW;   M = qw;    tr = false; }
    else{                    rel = tid-OFF_KWT;  M = kw;    tr = true; }
    int lane = rel & 31, t2 = rel >> 5;
    int nt = t2 % 16, kt = t2 / 16;
    int n = nt*8 + (lane >> 2), k0 = kt*16 + (lane & 3)*2;
    float v[4];
    #pragma unroll
    for (int q = 0; q < 4; q++){
        int k = k0 + (q >> 1)*8 + (q & 1);
        v[q] = tr ? M[(size_t)n*128 + k] : M[(size_t)k*128 + n];
    }
    float h[4], l[4];
    #pragma unroll
    for (int q = 0; q < 4; q++){
        h[q] = __bfloat162float(__float2bfloat16(v[q]));
        l[q] = v[q] - h[q];
    }
    uint4 o;
    o.x = packbf(h[0], h[1]); o.y = packbf(h[2], h[3]);
    o.z = packbf(l[0], l[1]); o.w = packbf(l[2], l[3]);
    g_frag[tid] = o;
}

// ---------------- prep: whh -> fp16 frags ----------------
__global__ void prep_whh16(const float* __restrict__ whh){
    int tid = blockIdx.x*blockDim.x + threadIdx.x;
    if (tid >= 4*12288) return;
    int v = tid / 12288, rel = tid % 12288;
    int lane = rel & 31, t2 = rel >> 5;
    int nt = t2 % 48, kt = t2 / 48;
    int n = nt*8 + (lane >> 2), k0 = kt*16 + (lane & 3)*2;
    const float* M = whh + (size_t)v*49152;   // [384][128], B[k][n] = M[n*128 + k]
    float v0 = M[(size_t)n*128 + k0],     v1 = M[(size_t)n*128 + k0 + 1];
    float v2 = M[(size_t)n*128 + k0 + 8], v3 = M[(size_t)n*128 + k0 + 9];
    g_imgU[(size_t)v*12288 + (size_t)(kt*48 + nt)*32 + lane] =
        make_uint2(packh(v0, v1), packh(v2, v3));
}

// ---------------- Wcomb = ggnn[v,i] @ wih[v]^T -> fp16 frags ----------------
__global__ __launch_bounds__(256)
void wcomb_prep(const float* __restrict__ ggnn, const float* __restrict__ wih){
    extern __shared__ float s[];
    float* As = s;
    float* Ws = s + 128*129;
    float* Cs = s + 2*128*129;
    int vi = blockIdx.x, cblk = blockIdx.y, v = vi >> 2;
    const float* A = ggnn + (size_t)vi*16384;
    const float* W = wih + ((size_t)v*H3 + cblk*128)*128;
    int tid = threadIdx.x;
    for (int i = tid; i < 16384; i += 256){
        int r = i >> 7, j = i & 127;
        As[j*129 + r] = A[i];
        Ws[j*129 + r] = W[i];
    }
    __syncthreads();
    int tx = tid & 15, ty = tid >> 4;
    float acc[8][8];
    #pragma unroll
    for (int a = 0; a < 8; a++)
        #pragma unroll
        for (int b = 0; b < 8; b++) acc[a][b] = 0.f;
    for (int j = 0; j < 128; j++){
        float av[8], wv[8];
        #pragma unroll
        for (int q = 0; q < 8; q++){
            av[q] = As[j*129 + ty*8 + q];
            wv[q] = Ws[j*129 + tx*8 + q];
        }
        #pragma unroll
        for (int a = 0; a < 8; a++)
            #pragma unroll
            for (int b = 0; b < 8; b++) acc[a][b] += av[a]*wv[b];
    }
    #pragma unroll
    for (int a = 0; a < 8; a++)
        #pragma unroll
        for (int b = 0; b < 8; b++)
            Cs[(ty*8+a)*128 + tx*8+b] = acc[a][b];
    __syncthreads();
    uint2* dst = g_imgW + (size_t)vi*12288;
    for (int it = tid; it < 4096; it += 256){
        int lane = it & 31, t2 = it >> 5;
        int lnt = t2 & 15, kt = t2 >> 4;
        int c = lnt*8 + (lane >> 2);
        int k0 = kt*16 + (lane & 3)*2;
        float v0 = Cs[k0*128 + c],       v1 = Cs[(k0+1)*128 + c];
        float v2 = Cs[(k0+8)*128 + c],   v3 = Cs[(k0+9)*128 + c];
        int ntg = cblk*16 + lnt;
        dst[(size_t)(kt*48 + ntg)*32 + lane] = make_uint2(packh(v0, v1), packh(v2, v3));
    }
}

// ---------------- HMMA GEMM bf16x3 (proj / q / qk) ----------------
__global__ __launch_bounds__(256)
void gemm_mma(const float* __restrict__ A, int lda, int M,
              const uint4* __restrict__ frag, int NT, int KT,
              const float* __restrict__ bias, float* __restrict__ C,
              int ldc, int act){
    int tid = threadIdx.x, wid = tid >> 5, lane = tid & 31;
    int wm = wid >> 1, wn = wid & 1;
    int gid = lane >> 2, tig = lane & 3;
    int rowBase = blockIdx.x*128 + wm*32 + gid;
    int ntG0 = blockIdx.y*16 + wn*8;

    float acc[2][8][4];
    #pragma unroll
    for (int mt = 0; mt < 2; mt++)
        #pragma unroll
        for (int nt = 0; nt < 8; nt++)
            #pragma unroll
            for (int q = 0; q < 4; q++) acc[mt][nt][q] = 0.f;

    float2 ax[2][4];
    auto loadA = [&](int kt){
        #pragma unroll
        for (int mt = 0; mt < 2; mt++){
            int r = rowBase + mt*16;
            int k = kt*16 + tig*2;
            bool p0 = (r < M), p1 = (r + 8 < M);
            const float* base0 = A + (size_t)r*lda + k;
            const float* base1 = A + (size_t)(r+8)*lda + k;
            ax[mt][0] = p0 ? *(const float2*)(base0)     : make_float2(0.f, 0.f);
            ax[mt][1] = p1 ? *(const float2*)(base1)     : make_float2(0.f, 0.f);
            ax[mt][2] = p0 ? *(const float2*)(base0 + 8) : make_float2(0.f, 0.f);
            ax[mt][3] = p1 ? *(const float2*)(base1 + 8) : make_float2(0.f, 0.f);
        }
    };
    loadA(0);
    uint4 bcur = frag[((size_t)(0*NT + ntG0))*32 + lane];

    for (int kt = 0; kt < KT; kt++){
        uint32_t Ah[2][4], Al[2][4];
        #pragma unroll
        for (int mt = 0; mt < 2; mt++){
            #pragma unroll
            for (int q = 0; q < 4; q++){
                float2 vv = ax[mt][q];
                float hx = __bfloat162float(__float2bfloat16(vv.x));
                float hy = __bfloat162float(__float2bfloat16(vv.y));
                Ah[mt][q] = packbf(vv.x, vv.y);
                Al[mt][q] = packbf(vv.x - hx, vv.y - hy);
            }
        }
        if (kt + 1 < KT) loadA(kt + 1);
        #pragma unroll
        for (int nt = 0; nt < 8; nt++){
            uint4 bn;
            if (nt < 7)           bn = frag[((size_t)(kt*NT + ntG0 + nt + 1))*32 + lane];
            else if (kt + 1 < KT) bn = frag[((size_t)((kt+1)*NT + ntG0))*32 + lane];
            else                  bn = bcur;
            #pragma unroll
            for (int mt = 0; mt < 2; mt++){
                MMA16816(acc[mt][nt], Ah[mt], bcur.x, bcur.y);
                MMA16816(acc[mt][nt], Ah[mt], bcur.z, bcur.w);
                MMA16816(acc[mt][nt], Al[mt], bcur.x, bcur.y);
            }
            bcur = bn;
        }
    }

    #pragma unroll
    for (int nt = 0; nt < 8; nt++){
        int col = (ntG0 + nt)*8 + tig*2;
        float b0 = 0.f, b1 = 0.f;
        if (bias){ b0 = bias[col]; b1 = bias[col + 1]; }
        #pragma unroll
        for (int mt = 0; mt < 2; mt++){
            int r = rowBase + mt*16;
            float v0 = acc[mt][nt][0] + b0, v1 = acc[mt][nt][1] + b1;
            float v2 = acc[mt][nt][2] + b0, v3 = acc[mt][nt][3] + b1;
            if (act == 1){ v0 = tanhf(v0); v1 = tanhf(v1); v2 = tanhf(v2); v3 = tanhf(v3); }
            if (r < M)     *(float2*)(C + (size_t)r*ldc + col)     = make_float2(v0, v1);
            if (r + 8 < M) *(float2*)(C + (size_t)(r+8)*ldc + col) = make_float2(v2, v3);
        }
    }
}

// ---------------- fused GRU cell v7: fp16 single-pass (3x fewer HMMA) ----------------
// 8 warps = 4 gates x 2 col-slices (64 cols, 8 nt).
#define GPASS(SA, FP, GATE, ACC) \
  _Pragma("unroll 1") \
  for (int kt = 0; kt < 8; kt++){ \
    uint4 fh0 = (SA)[(0*8 + kt)*32 + lane]; \
    uint4 fh1 = (SA)[(1*8 + kt)*32 + lane]; \
    uint32_t A0[4] = {fh0.x, fh0.y, fh0.z, fh0.w}; \
    uint32_t A1[4] = {fh1.x, fh1.y, fh1.z, fh1.w}; \
    _Pragma("unroll") \
    for (int nt = 0; nt < 8; nt++){ \
      uint2 b = (FP)[(size_t)(kt*48 + (GATE)*16 + sub*8 + nt)*32 + lane]; \
      MMAF16(ACC[0][nt], A0, b.x, b.y); \
      MMAF16(ACC[1][nt], A1, b.x, b.y); \
    } \
  }

__global__ __launch_bounds__(256, 2)
void gru_fused(const float* __restrict__ Hin, float* __restrict__ Hout,
               const uint2* __restrict__ wcF, const uint2* __restrict__ whhF,
               const float* __restrict__ bih, const float* __restrict__ bhh,
               const int* __restrict__ rowptrB, size_t hinStride){
    extern __shared__ char sm[];
    uint4* sAg   = (uint4*)sm;             // fp16 frags G (8KB used of 16KB) | post-MMA: gate r
    uint4* sH    = (uint4*)(sm + 16384);   // fp16 frags h                   | post-MMA: gate z
    float* sHval = (float*)(sm + 32768);   // 32*128 fp32 (16KB), live
    float* sAval = (float*)(sm + 49152);   // 16KB                           | post-MMA: gate inn
    float* sbias = (float*)(sm + 65536);   // 512 f (2KB)
    float* sGn   = (float*)(sm + 67584);   // 16KB gate hn
    float* sGr   = (float*)sm;
    float* sGz   = (float*)(sm + 16384);
    float* sGi   = sAval;
    int tid = threadIdx.x, wid = tid >> 5, lane = tid & 31;
    int gid = lane >> 2, tig = lane & 3;

    int v   = blockIdx.x / GRU_GRID;
    int blk = blockIdx.x % GRU_GRID;
    int m0 = blk*32;
    const float* Hsrc = Hin + (size_t)v * hinStride;
    Hout   += (size_t)v * NN * HH;
    wcF    += (size_t)v * 49152;   // 4 layers * 12288 per view
    whhF   += (size_t)v * 12288;
    bih    += v * H3;
    bhh    += v * H3;
    const int* rowptr = rowptrB + v * NN;

    if (tid < 128){
        sbias[tid]     = bih[tid]     + bhh[tid];
        sbias[128+tid] = bih[128+tid] + bhh[128+tid];
        sbias[256+tid] = bih[256+tid];
        sbias[384+tid] = bhh[256+tid];
    }
    // h tile (32 rows)
    for (int it = tid; it < 32*32; it += 256){
        int r = it >> 5, c4 = it & 31;
        float4 hv = make_float4(0.f,0.f,0.f,0.f);
        if (m0 + r < NN) hv = *(const float4*)(Hsrc + (size_t)(m0+r)*HH + c4*4);
        *(float4*)(sHval + r*128 + c4*4) = hv;
    }
    // CSR gather (4 rows per warp)
    for (int rr = wid; rr < 32; rr += 8){
        int grow = m0 + rr;
        float4 acc = make_float4(0.f,0.f,0.f,0.f);
        if (grow < NN){
            int s = rowptr[grow], e = rowptr[grow + 1];
            int idx = s;
            while (idx + 4 <= e){
                int a0 = g_csrsrc[idx], a1 = g_csrsrc[idx+1];
                int a2 = g_csrsrc[idx+2], a3 = g_csrsrc[idx+3];
                float4 v0 = *(const float4*)(Hsrc + (size_t)a0*HH + lane*4);
                float4 v1 = *(const float4*)(Hsrc + (size_t)a1*HH + lane*4);
                float4 v2 = *(const float4*)(Hsrc + (size_t)a2*HH + lane*4);
                float4 v3 = *(const float4*)(Hsrc + (size_t)a3*HH + lane*4);
                acc.x += v0.x + v1.x + v2.x + v3.x;
                acc.y += v0.y + v1.y + v2.y + v3.y;
                acc.z += v0.z + v1.z + v2.z + v3.z;
                acc.w += v0.w + v1.w + v2.w + v3.w;
                idx += 4;
            }
            while (idx < e){
                int a0 = g_csrsrc[idx];
                float4 v0 = *(const float4*)(Hsrc + (size_t)a0*HH + lane*4);
                acc.x += v0.x; acc.y += v0.y; acc.z += v0.z; acc.w += v0.w;
                idx++;
            }
        }
        *(float4*)(sAval + rr*128 + lane*4) = acc;
    }
    __syncthreads();
    // pack G + h into fp16 fragments (2 mt x 8 kt x 32 lanes = 512 items)
    for (int it = tid; it < 512; it += 256){
        int mt = it >> 8, kt = (it >> 5) & 7, ln = it & 31;
        int g = ln >> 2, tg = ln & 3;
        int r0 = mt*16 + g, r1 = r0 + 8;
        int k = kt*16 + tg*2;
        float2 a00 = *(const float2*)(sAval + r0*128 + k);
        float2 a01 = *(const float2*)(sAval + r0*128 + k + 8);
        float2 a10 = *(const float2*)(sAval + r1*128 + k);
        float2 a11 = *(const float2*)(sAval + r1*128 + k + 8);
        sAg[(mt*8 + kt)*32 + ln] = make_uint4(packh(a00.x, a00.y), packh(a10.x, a10.y),
                                              packh(a01.x, a01.y), packh(a11.x, a11.y));
        float2 h00 = *(const float2*)(sHval + r0*128 + k);
        float2 h01 = *(const float2*)(sHval + r0*128 + k + 8);
        float2 h10 = *(const float2*)(sHval + r1*128 + k);
        float2 h11 = *(const float2*)(sHval + r1*128 + k + 8);
        sH[(mt*8 + kt)*32 + ln] = make_uint4(packh(h00.x, h00.y), packh(h10.x, h10.y),
                                             packh(h01.x, h01.y), packh(h11.x, h11.y));
    }
    __syncthreads();

    // MMA phase: warp = (gate g, col slice sub of 64 cols)
    int g = wid >> 1, sub = wid & 1;
    float acc[2][8][4];
    #pragma unroll
    for (int mt = 0; mt < 2; mt++)
        #pragma unroll
        for (int nt = 0; nt < 8; nt++)
            #pragma unroll
            for (int q = 0; q < 4; q++) acc[mt][nt][q] = 0.f;

    if (g == 0){ GPASS(sAg, wcF, 0, acc); GPASS(sH, whhF, 0, acc); }
    else if (g == 1){ GPASS(sAg, wcF, 1, acc); GPASS(sH, whhF, 1, acc); }
    else if (g == 2){ GPASS(sAg, wcF, 2, acc); }
    else            { GPASS(sH, whhF, 2, acc); }

    __syncthreads();

    // dump gate accumulators [32][128] per gate
    {
        float* gout = (g == 0) ? sGr : (g == 1) ? sGz : (g == 2) ? sGi : sGn;
        #pragma unroll
        for (int mt = 0; mt < 2; mt++){
            #pragma unroll
            for (int nt = 0; nt < 8; nt++){
                int col = sub*64 + nt*8 + tig*2;
                int r0 = mt*16 + gid;
                *(float2*)(gout + r0*128 + col)     = make_float2(acc[mt][nt][0], acc[mt][nt][1]);
                *(float2*)(gout + (r0+8)*128 + col) = make_float2(acc[mt][nt][2], acc[mt][nt][3]);
            }
        }
    }
    __syncthreads();

    // epilogue: warp per row (4 rows/warp), lane = 4 cols
    for (int rr = wid; rr < 32; rr += 8){
        int grow = m0 + rr;
        if (grow >= NN) continue;
        int col = lane*4;
        float4 r4 = *(float4*)(sGr + rr*128 + col);
        float4 z4 = *(float4*)(sGz + rr*128 + col);
        float4 i4 = *(float4*)(sGi + rr*128 + col);
        float4 n4 = *(float4*)(sGn + rr*128 + col);
        float4 h4 = *(float4*)(sHval + rr*128 + col);
        float4 br = *(float4*)(sbias + col);
        float4 bz = *(float4*)(sbias + 128 + col);
        float4 bi = *(float4*)(sbias + 256 + col);
        float4 bh = *(float4*)(sbias + 384 + col);
        float4 o;
        {
            float r_ = sigm(r4.x + br.x), z_ = sigm(z4.x + bz.x);
            float n_ = tanhf(i4.x + bi.x + r_*(n4.x + bh.x));
            o.x = (1.f - z_)*n_ + z_*h4.x;
        }
        {
            float r_ = sigm(r4.y + br.y), z_ = sigm(z4.y + bz.y);
            float n_ = tanhf(i4.y + bi.y + r_*(n4.y + bh.y));
            o.y = (1.f - z_)*n_ + z_*h4.y;
        }
        {
            float r_ = sigm(r4.z + br.z), z_ = sigm(z4.z + bz.z);
            float n_ = tanhf(i4.z + bi.z + r_*(n4.z + bh.z));
            o.z = (1.f - z_)*n_ + z_*h4.z;
        }
        {
            float r_ = sigm(r4.w + br.w), z_ = sigm(z4.w + bz.w);
            float n_ = tanhf(i4.w + bi.w + r_*(n4.w + bh.w));
            o.w = (1.f - z_)*n_ + z_*h4.w;
        }
        *(float4*)(Hout + (size_t)grow*HH + col) = o;
    }
}

// ---------------- LN + GELU after projection (warp per row) ----------------
__global__ void ln_gelu(const float* __restrict__ lnw, const float* __restrict__ lnb){
    int gw = (blockIdx.x*blockDim.x + threadIdx.x) >> 5;
    if (gw >= NN) return;
    int lane = threadIdx.x & 31;
    float xv[4], s = 0.f, s2 = 0.f;
    #pragma unroll
    for (int i = 0; i < 4; i++){
        xv[i] = g_proj[(size_t)gw*HH + lane + 32*i];
        s += xv[i]; s2 += xv[i]*xv[i];
    }
    #pragma unroll
    for (int o = 16; o; o >>= 1){
        s  += __shfl_xor_sync(0xffffffffu, s,  o);
        s2 += __shfl_xor_sync(0xffffffffu, s2, o);
    }
    float mu = s*(1.f/HH), var = s2*(1.f/HH) - mu*mu;
    float rstd = rsqrtf(var + 1e-5f);
    #pragma unroll
    for (int i = 0; i < 4; i++){
        int j = lane + 32*i;
        float y = (xv[i] - mu)*rstd*lnw[j] + lnb[j];
        g_h0[(size_t)gw*HH + j] = 0.5f*y*(1.f + erff(y*0.7071067811865476f));
    }
}

// ---------------- fused: per-view LN + residual + attention ----------
__global__ void ln_attn(const float* __restrict__ hall,
                        const float* __restrict__ vlnw, const float* __restrict__ vlnb){
    int gw = (blockIdx.x*blockDim.x + threadIdx.x) >> 5;
    if (gw >= NN) return;
    int lane = threadIdx.x & 31;
    float h0v[4], qkv[4];
    #pragma unroll
    for (int i = 0; i < 4; i++){
        h0v[i] = g_h0[(size_t)gw*HH + lane + 32*i];
        qkv[i] = g_qk[(size_t)gw*HH + lane + 32*i];
    }
    float y[4][4], sc[4];
    #pragma unroll
    for (int v = 0; v < 4; v++){
        float xv[4], s = 0.f, s2 = 0.f;
        #pragma unroll
        for (int i = 0; i < 4; i++){
            xv[i] = hall[((size_t)v*NN + gw)*HH + lane + 32*i];
            s += xv[i]; s2 += xv[i]*xv[i];
        }
        #pragma unroll
        for (int o = 16; o; o >>= 1){
            s  += __shfl_xor_sync(0xffffffffu, s,  o);
            s2 += __shfl_xor_sync(0xffffffffu, s2, o);
        }
        float mu = s*(1.f/HH), var = s2*(1.f/HH) - mu*mu;
        float rstd = rsqrtf(var + 1e-5f);
        float p = 0.f;
        #pragma unroll
        for (int i = 0; i < 4; i++){
            int j = lane + 32*i;
            y[v][i] = (xv[i] - mu)*rstd*vlnw[v*HH + j] + vlnb[v*HH + j] + h0v[i];
            p += qkv[i]*y[v][i];
        }
        #pragma unroll
        for (int o = 16; o; o >>= 1) p += __shfl_xor_sync(0xffffffffu, p, o);
        sc[v] = p * 0.08838834764831845f;
    }
    float mx = fmaxf(fmaxf(sc[0], sc[1]), fmaxf(sc[2], sc[3]));
    float ex[4], sum = 0.f;
    #pragma unroll
    for (int v = 0; v < 4; v++){ ex[v] = expf(sc[v] - mx); sum += ex[v]; }
    float inv = 1.f/sum;
    #pragma unroll
    for (int i = 0; i < 4; i++){
        float o = 0.f;
        #pragma unroll
        for (int v = 0; v < 4; v++) o += ex[v]*inv*y[v][i];
        g_fused[(size_t)gw*HH + lane + 32*i] = o;
    }
}

// ---------------- pooling ----------------
__global__ void pool_init(){
    int i = blockIdx.x*blockDim.x + threadIdx.x;
    if (i < BB*HH){ g_psum[i] = 0.f; g_pmax[i] = 0u; }
    if (i < BB) g_cnt[i] = 0.f;
}
__global__ void pool_acc(const int* __restrict__ batch){
    int j = threadIdx.x;
    int n0 = blockIdx.x * 64;
    int cur = -1; float sum = 0.f, mx = -1e30f; int cnt = 0;
    for (int t = 0; t < 64; t++){
        int n = n0 + t;
        if (n >= NN) break;
        int b = batch[n];
        if (b != cur){
            if (cur >= 0){
                atomicAdd(&g_psum[cur*HH + j], sum);
                atomicMax(&g_pmax[cur*HH + j], fenc(mx));
                if (j == 0) atomicAdd(&g_cnt[cur], (float)cnt);
            }
            cur = b; sum = 0.f; mx = -1e30f; cnt = 0;
        }
        float f = g_fused[(size_t)n*HH + j];
        sum += f; mx = fmaxf(mx, f); cnt++;
    }
    if (cur >= 0){
        atomicAdd(&g_psum[cur*HH + j], sum);
        atomicMax(&g_pmax[cur*HH + j], fenc(mx));
        if (j == 0) atomicAdd(&g_cnt[cur], (float)cnt);
    }
}

// ---------------- classifier ----------------
__global__ void classifier(const float* __restrict__ c1w, const float* __restrict__ c1b,
                           const float* __restrict__ c2w, const float* __restrict__ c2b,
                           const float* __restrict__ c3w, const float* __restrict__ c3b,
                           float* __restrict__ out){
    __shared__ float gsh[2*HH], h1[HH], h2[64];
    int b = blockIdx.x, j = threadIdx.x;
    float cnt = fmaxf(g_cnt[b], 1.f);
    gsh[j]      = g_psum[b*HH + j] / cnt;
    gsh[HH + j] = fdec(g_pmax[b*HH + j]);
    __syncthreads();
    float a = c1b[j];
    for (int k = 0; k < 2*HH; k++) a += gsh[k]*c1w[k*HH + j];
    h1[j] = fmaxf(a, 0.f);
    __syncthreads();
    if (j < 64){
        float a2 = c2b[j];
        for (int k = 0; k < HH; k++) a2 += h1[k]*c2w[k*64 + j];
        h2[j] = fmaxf(a2, 0.f);
    }
    __syncthreads();
    if (j == 0){
        float o = c3b[0];
        for (int k = 0; k < 64; k++) o += h2[k]*c3w[k];
        out[b] = o;
    }
}

// ---------------- launch ----------------
extern "C" void kernel_launch(void* const* d_in, const int* in_sizes, int n_in,
                              void* d_out, int out_size){
    (void)in_sizes; (void)n_in; (void)out_size;
    const float* x      = (const float*)d_in[0];
    const int*   ei     = (const int*)  d_in[1];
    const int*   et     = (const int*)  d_in[2];
    const int*   batch  = (const int*)  d_in[3];
    const float* proj_w = (const float*)d_in[4];
    const float* proj_b = (const float*)d_in[5];
    const float* ln0w   = (const float*)d_in[6];
    const float* ln0b   = (const float*)d_in[7];
    const float* ggnn   = (const float*)d_in[8];
    const float* wih    = (const float*)d_in[9];
    const float* whh    = (const float*)d_in[10];
    const float* bih    = (const float*)d_in[11];
    const float* bhh    = (const float*)d_in[12];
    const float* vlnw   = (const float*)d_in[13];
    const float* vlnb   = (const float*)d_in[14];
    const float* qw     = (const float*)d_in[15];
    const float* qb     = (const float*)d_in[16];
    const float* kw     = (const float*)d_in[17];
    /* kb unused: softmax-invariant */
    const float* c1w    = (const float*)d_in[19];
    const float* c1b    = (const float*)d_in[20];
    const float* c2w    = (const float*)d_in[21];
    const float* c2b    = (const float*)d_in[22];
    const float* c3w    = (const float*)d_in[23];
    const float* c3b    = (const float*)d_in[24];
    float* out = (float*)d_out;

    float *p_h0, *p_hallA, *p_hallB, *p_proj, *p_q, *p_qk;
    uint4 *p_frag;
    uint2 *p_imgW, *p_imgU;
    int* p_rowptr;
    cudaGetSymbolAddress((void**)&p_h0,    g_h0);
    cudaGetSymbolAddress((void**)&p_hallA, g_hallA);
    cudaGetSymbolAddress((void**)&p_hallB, g_hallB);
    cudaGetSymbolAddress((void**)&p_proj,  g_proj);
    cudaGetSymbolAddress((void**)&p_q,     g_q);
    cudaGetSymbolAddress((void**)&p_qk,    g_qk);
    cudaGetSymbolAddress((void**)&p_frag,  g_frag);
    cudaGetSymbolAddress((void**)&p_imgW,  g_imgW);
    cudaGetSymbolAddress((void**)&p_imgU,  g_imgU);
    cudaGetSymbolAddress((void**)&p_rowptr, g_rowptr);

    const int GRU_SMEM = 83968;   // 82KB -> 2 CTAs/SM
    cudaFuncSetAttribute(gru_fused, cudaFuncAttributeMaxDynamicSharedMemorySize, GRU_SMEM);
    const int WC_SMEM = (2*128*129 + 128*128) * 4;
    cudaFuncSetAttribute(wcomb_prep, cudaFuncAttributeMaxDynamicSharedMemorySize, WC_SMEM);

    const size_t NH = (size_t)NN*HH;

    csr_zero<<<(SEGN + 255)/256, 256>>>();
    csr_count<<<(EE + 255)/256, 256>>>(ei, et);
    csr_scan1<<<SCAN_BLKS, 1024>>>();
    csr_scan2<<<1, 1024>>>();
    csr_scan3<<<(SEGN + 255)/256, 256>>>();
    csr_fill<<<(EE + 255)/256, 256>>>(ei, et);

    prep_frags<<<(FRAG_TOTAL + 255)/256, 256>>>(proj_w, qw, kw);
    prep_whh16<<<(4*12288 + 255)/256, 256>>>(whh);
    wcomb_prep<<<dim3(16,3), 256, WC_SMEM>>>(ggnn, wih);

    gemm_mma<<<dim3(MT,1), 256>>>(x, INF_, NN, p_frag + OFF_PROJ, 16, 32, proj_b, p_proj, HH, 0);
    ln_gelu<<<(NN*32 + 255)/256, 256>>>(ln0w, ln0b);

    gemm_mma<<<dim3(MT,1), 256>>>(p_h0, HH, NN, p_frag + OFF_QW, 16, 8, qb, p_q, HH, 1);
    gemm_mma<<<dim3(MT,1), 256>>>(p_q, HH, NN, p_frag + OFF_KWT, 16, 8, nullptr, p_qk, HH, 0);

    float* bufs[2] = { p_hallA, p_hallB };
    const float* hin = p_h0;
    size_t hinStride = 0;
    float* hout = p_hallA;
    for (int i = 0; i < 4; i++){
        gru_fused<<<4*GRU_GRID, 256, GRU_SMEM>>>(hin, hout,
            p_imgW + (size_t)i*12288, p_imgU,
            bih, bhh, p_rowptr, hinStride);
        hin = hout;
        hinStride = NH;
        hout = bufs[(i + 1) & 1];
    }
    const float* hfinal = hin;

    ln_attn<<<(NN*32 + 255)/256, 256>>>(hfinal, vlnw, vlnb);

    pool_init<<<(BB*HH + 255)/256, 256>>>();
    pool_acc<<<(NN + 63)/64, 128>>>(batch);
    classifier<<<BB, 128>>>(c1w, c1b, c2w, c2b, c3w, c3b, out);
}

// round 17
// speedup vs baseline: 2.6567x; 1.2396x over previous
#include <cuda_runtime.h>
#include <cuda_bf16.h>
#include <cuda_fp16.h>
#include <cstdint>
#include <math.h>

#define NN   50000
#define EE   600000
#define INF_ 512
#define HH   128
#define H3   384
#define BB   64
#define MT   ((NN + 127) / 128)
#define SEGN (4*NN)
#define SCAN_BLKS ((SEGN + 1023)/1024)
#define GRU_GRID ((NN + 31)/32)

// ---------------- device scratch ----------------
__device__ float g_h0   [(size_t)NN*HH];
__device__ float g_hallA[(size_t)4*NN*HH];
__device__ float g_hallB[(size_t)4*NN*HH];
__device__ float g_proj [(size_t)NN*HH];
__device__ float g_q    [(size_t)NN*HH];
__device__ float g_qk   [(size_t)NN*HH];
__device__ float g_fused[(size_t)NN*HH];
__device__ float g_psum[BB*HH];
__device__ unsigned g_pmax[BB*HH];
__device__ float g_cnt [BB];

__device__ int g_deg   [SEGN];
__device__ int g_scanT [SEGN];
__device__ int g_part  [SCAN_BLKS];
__device__ int g_partS [SCAN_BLKS];
__device__ int g_rowptr[SEGN + 1];
__device__ int g_woff  [SEGN];
__device__ int g_csrsrc[EE];

// fp16 single-pass frags for proj/q/qk
#define OFF_PROJ 0
#define OFF_QW   16384
#define OFF_KWT  20480
#define FRAG_TOTAL 24576
__device__ uint2 g_frag16[FRAG_TOTAL];

// fp16 single-pass frags for GRU weights: per matrix 8kt x 48nt x 32lane uint2 = 12288
__device__ uint2 g_imgW[16u*12288u];   // Wcomb[v][i]
__device__ uint2 g_imgU[ 4u*12288u];   // Whh[v]

__constant__ int c_v_of_t[13] = {0,1,1,1,2,2,2,3,3,0,0,3,3};

// ---------------- helpers ----------------
__device__ __forceinline__ uint32_t packh(float a, float b){
    __half2 t = __floats2half2_rn(a, b);
    return *reinterpret_cast<uint32_t*>(&t);
}
__device__ __forceinline__ unsigned fenc(float f){
    unsigned b = __float_as_uint(f);
    return (b & 0x80000000u) ? ~b : (b | 0x80000000u);
}
__device__ __forceinline__ float fdec(unsigned u){
    return __uint_as_float((u & 0x80000000u) ? (u & 0x7fffffffu) : ~u);
}
__device__ __forceinline__ float sigm(float x){ return 1.f/(1.f + expf(-x)); }

#define MMAF16(d, a, b0_, b1_) \
  asm volatile("mma.sync.aligned.m16n8k16.row.col.f32.f16.f16.f32 " \
    "{%0,%1,%2,%3}, {%4,%5,%6,%7}, {%8,%9}, {%0,%1,%2,%3};" \
    : "+f"((d)[0]), "+f"((d)[1]), "+f"((d)[2]), "+f"((d)[3]) \
    : "r"((a)[0]), "r"((a)[1]), "r"((a)[2]), "r"((a)[3]), "r"(b0_), "r"(b1_))

// ---------------- CSR build ----------------
__global__ void csr_zero(){
    int i = blockIdx.x*blockDim.x + threadIdx.x;
    if (i < SEGN) g_deg[i] = 0;
}
__global__ void csr_count(const int* __restrict__ ei, const int* __restrict__ et){
    int e = blockIdx.x*blockDim.x + threadIdx.x;
    if (e >= EE) return;
    int v = c_v_of_t[et[e]];
    atomicAdd(&g_deg[v*NN + ei[EE + e]], 1);
}
__global__ void csr_scan1(){
    __shared__ int sm[1024];
    int t = threadIdx.x, b = blockIdx.x;
    int i = b*1024 + t;
    int v = (i < SEGN) ? g_deg[i] : 0;
    sm[t] = v;
    __syncthreads();
    #pragma unroll
    for (int o = 1; o < 1024; o <<= 1){
        int add = (t >= o) ? sm[t - o] : 0;
        __syncthreads();
        sm[t] += add;
        __syncthreads();
    }
    if (i < SEGN) g_scanT[i] = sm[t];
    if (t == 1023) g_part[b] = sm[1023];
}
__global__ void csr_scan2(){
    __shared__ int sm[SCAN_BLKS];
    int t = threadIdx.x;
    if (t < SCAN_BLKS) sm[t] = g_part[t];
    __syncthreads();
    if (t == 0){
        int run = 0;
        for (int i = 0; i < SCAN_BLKS; i++){ run += sm[i]; g_partS[i] = run; }
    }
}
__global__ void csr_scan3(){
    int i = blockIdx.x*blockDim.x + threadIdx.x;
    if (i >= SEGN) return;
    int b = i >> 10;
    int base = (b > 0) ? g_partS[b-1] : 0;
    int excl = base + g_scanT[i] - g_deg[i];
    g_rowptr[i] = excl;
    g_woff[i]   = excl;
    if (i == 0) g_rowptr[SEGN] = EE;
}
__global__ void csr_fill(const int* __restrict__ ei, const int* __restrict__ et){
    int e = blockIdx.x*blockDim.x + threadIdx.x;
    if (e >= EE) return;
    int v = c_v_of_t[et[e]];
    int pos = atomicAdd(&g_woff[v*NN + ei[EE + e]], 1);
    g_csrsrc[pos] = ei[e];
}

// ---------------- prep: proj/qw/kw^T -> fp16 frags ----------------
__global__ void prep_frags16(const float* __restrict__ projw,
                             const float* __restrict__ qw, const float* __restrict__ kw){
    int tid = blockIdx.x*blockDim.x + threadIdx.x;
    if (tid >= FRAG_TOTAL) return;
    const float* M; int rel; bool tr;
    if (tid < OFF_QW){       rel = tid;          M = projw; tr = false; }
    else if (tid < OFF_KWT){ rel = tid-OFF_QW;   M = qw;    tr = false; }
    else{                    rel = tid-OFF_KWT;  M = kw;    tr = true; }
    int lane = rel & 31, t2 = rel >> 5;
    int nt = t2 % 16, kt = t2 / 16;
    int n = nt*8 + (lane >> 2), k0 = kt*16 + (lane & 3)*2;
    float v[4];
    #pragma unroll
    for (int q = 0; q < 4; q++){
        int k = k0 + (q >> 1)*8 + (q & 1);
        v[q] = tr ? M[(size_t)n*128 + k] : M[(size_t)k*128 + n];
    }
    g_frag16[tid] = make_uint2(packh(v[0], v[1]), packh(v[2], v[3]));
}

// ---------------- prep: whh -> fp16 frags ----------------
__global__ void prep_whh16(const float* __restrict__ whh){
    int tid = blockIdx.x*blockDim.x + threadIdx.x;
    if (tid >= 4*12288) return;
    int v = tid / 12288, rel = tid % 12288;
    int lane = rel & 31, t2 = rel >> 5;
    int nt = t2 % 48, kt = t2 / 48;
    int n = nt*8 + (lane >> 2), k0 = kt*16 + (lane & 3)*2;
    const float* M = whh + (size_t)v*49152;
    float v0 = M[(size_t)n*128 + k0],     v1 = M[(size_t)n*128 + k0 + 1];
    float v2 = M[(size_t)n*128 + k0 + 8], v3 = M[(size_t)n*128 + k0 + 9];
    g_imgU[(size_t)v*12288 + (size_t)(kt*48 + nt)*32 + lane] =
        make_uint2(packh(v0, v1), packh(v2, v3));
}

// ---------------- Wcomb = ggnn[v,i] @ wih[v]^T -> fp16 frags ----------------
__global__ __launch_bounds__(256)
void wcomb_prep(const float* __restrict__ ggnn, const float* __restrict__ wih){
    extern __shared__ float s[];
    float* As = s;
    float* Ws = s + 128*129;
    float* Cs = s + 2*128*129;
    int vi = blockIdx.x, cblk = blockIdx.y, v = vi >> 2;
    const float* A = ggnn + (size_t)vi*16384;
    const float* W = wih + ((size_t)v*H3 + cblk*128)*128;
    int tid = threadIdx.x;
    for (int i = tid; i < 16384; i += 256){
        int r = i >> 7, j = i & 127;
        As[j*129 + r] = A[i];
        Ws[j*129 + r] = W[i];
    }
    __syncthreads();
    int tx = tid & 15, ty = tid >> 4;
    float acc[8][8];
    #pragma unroll
    for (int a = 0; a < 8; a++)
        #pragma unroll
        for (int b = 0; b < 8; b++) acc[a][b] = 0.f;
    for (int j = 0; j < 128; j++){
        float av[8], wv[8];
        #pragma unroll
        for (int q = 0; q < 8; q++){
            av[q] = As[j*129 + ty*8 + q];
            wv[q] = Ws[j*129 + tx*8 + q];
        }
        #pragma unroll
        for (int a = 0; a < 8; a++)
            #pragma unroll
            for (int b = 0; b < 8; b++) acc[a][b] += av[a]*wv[b];
    }
    #pragma unroll
    for (int a = 0; a < 8; a++)
        #pragma unroll
        for (int b = 0; b < 8; b++)
            Cs[(ty*8+a)*128 + tx*8+b] = acc[a][b];
    __syncthreads();
    uint2* dst = g_imgW + (size_t)vi*12288;
    for (int it = tid; it < 4096; it += 256){
        int lane = it & 31, t2 = it >> 5;
        int lnt = t2 & 15, kt = t2 >> 4;
        int c = lnt*8 + (lane >> 2);
        int k0 = kt*16 + (lane & 3)*2;
        float v0 = Cs[k0*128 + c],       v1 = Cs[(k0+1)*128 + c];
        float v2 = Cs[(k0+8)*128 + c],   v3 = Cs[(k0+9)*128 + c];
        int ntg = cblk*16 + lnt;
        dst[(size_t)(kt*48 + ntg)*32 + lane] = make_uint2(packh(v0, v1), packh(v2, v3));
    }
}

// ---------------- fp16 single-pass HMMA GEMM (proj / q / qk) ----------------
__global__ __launch_bounds__(256)
void gemm_mma16(const float* __restrict__ A, int lda, int M,
                const uint2* __restrict__ frag, int NT, int KT,
                const float* __restrict__ bias, float* __restrict__ C,
                int ldc, int act){
    int tid = threadIdx.x, wid = tid >> 5, lane = tid & 31;
    int wm = wid >> 1, wn = wid & 1;
    int gid = lane >> 2, tig = lane & 3;
    int rowBase = blockIdx.x*128 + wm*32 + gid;
    int ntG0 = blockIdx.y*16 + wn*8;

    float acc[2][8][4];
    #pragma unroll
    for (int mt = 0; mt < 2; mt++)
        #pragma unroll
        for (int nt = 0; nt < 8; nt++)
            #pragma unroll
            for (int q = 0; q < 4; q++) acc[mt][nt][q] = 0.f;

    float2 ax[2][4];
    auto loadA = [&](int kt){
        #pragma unroll
        for (int mt = 0; mt < 2; mt++){
            int r = rowBase + mt*16;
            int k = kt*16 + tig*2;
            bool p0 = (r < M), p1 = (r + 8 < M);
            const float* base0 = A + (size_t)r*lda + k;
            const float* base1 = A + (size_t)(r+8)*lda + k;
            ax[mt][0] = p0 ? *(const float2*)(base0)     : make_float2(0.f, 0.f);
            ax[mt][1] = p1 ? *(const float2*)(base1)     : make_float2(0.f, 0.f);
            ax[mt][2] = p0 ? *(const float2*)(base0 + 8) : make_float2(0.f, 0.f);
            ax[mt][3] = p1 ? *(const float2*)(base1 + 8) : make_float2(0.f, 0.f);
        }
    };
    loadA(0);
    uint2 bcur = frag[((size_t)(0*NT + ntG0))*32 + lane];

    for (int kt = 0; kt < KT; kt++){
        uint32_t Ah[2][4];
        #pragma unroll
        for (int mt = 0; mt < 2; mt++){
            #pragma unroll
            for (int q = 0; q < 4; q++){
                float2 vv = ax[mt][q];
                Ah[mt][q] = packh(vv.x, vv.y);
            }
        }
        if (kt + 1 < KT) loadA(kt + 1);
        #pragma unroll
        for (int nt = 0; nt < 8; nt++){
            uint2 bn;
            if (nt < 7)           bn = frag[((size_t)(kt*NT + ntG0 + nt + 1))*32 + lane];
            else if (kt + 1 < KT) bn = frag[((size_t)((kt+1)*NT + ntG0))*32 + lane];
            else                  bn = bcur;
            #pragma unroll
            for (int mt = 0; mt < 2; mt++)
                MMAF16(acc[mt][nt], Ah[mt], bcur.x, bcur.y);
            bcur = bn;
        }
    }

    #pragma unroll
    for (int nt = 0; nt < 8; nt++){
        int col = (ntG0 + nt)*8 + tig*2;
        float b0 = 0.f, b1 = 0.f;
        if (bias){ b0 = bias[col]; b1 = bias[col + 1]; }
        #pragma unroll
        for (int mt = 0; mt < 2; mt++){
            int r = rowBase + mt*16;
            float v0 = acc[mt][nt][0] + b0, v1 = acc[mt][nt][1] + b1;
            float v2 = acc[mt][nt][2] + b0, v3 = acc[mt][nt][3] + b1;
            if (act == 1){ v0 = tanhf(v0); v1 = tanhf(v1); v2 = tanhf(v2); v3 = tanhf(v3); }
            if (r < M)     *(float2*)(C + (size_t)r*ldc + col)     = make_float2(v0, v1);
            if (r + 8 < M) *(float2*)(C + (size_t)(r+8)*ldc + col) = make_float2(v2, v3);
        }
    }
}

// ---------------- fused GRU cell v8: fp16, half-split acc, fp16 gates, 3 CTAs/SM -----
// 8 warps = 4 gates x 2 col-slices of 64 cols. nt processed in 2 halves of 4.
#define GPASS_H(SA, FP, GATE, HALF, ACC) \
  _Pragma("unroll 1") \
  for (int kt = 0; kt < 8; kt++){ \
    uint4 fh0 = (SA)[(0*8 + kt)*32 + lane]; \
    uint4 fh1 = (SA)[(1*8 + kt)*32 + lane]; \
    uint32_t A0[4] = {fh0.x, fh0.y, fh0.z, fh0.w}; \
    uint32_t A1[4] = {fh1.x, fh1.y, fh1.z, fh1.w}; \
    _Pragma("unroll") \
    for (int nt = 0; nt < 4; nt++){ \
      uint2 b = (FP)[(size_t)(kt*48 + (GATE)*16 + sub*8 + (HALF)*4 + nt)*32 + lane]; \
      MMAF16(ACC[0][nt], A0, b.x, b.y); \
      MMAF16(ACC[1][nt], A1, b.x, b.y); \
    } \
  }

// dump half's acc to fp16 gate buffer with bank-rotation layout
#define GDUMP(G2, HALF, ACC) \
  _Pragma("unroll") \
  for (int mt = 0; mt < 2; mt++){ \
    int r0 = mt*16 + gid, r1 = r0 + 8; \
    _Pragma("unroll") \
    for (int nt = 0; nt < 4; nt++){ \
      int c2 = (sub*64 + (HALF)*32 + nt*8 + tig*2) >> 1; \
      (G2)[r0*64 + ((c2 + r0*4) & 63)] = __floats2half2_rn(ACC[mt][nt][0], ACC[mt][nt][1]); \
      (G2)[r1*64 + ((c2 + r1*4) & 63)] = __floats2half2_rn(ACC[mt][nt][2], ACC[mt][nt][3]); \
    } \
  }

__device__ __forceinline__ float2 gread(const __half2* g2, int rr, int c2){
    return __half22float2(g2[rr*64 + ((c2 + rr*4) & 63)]);
}

__global__ __launch_bounds__(256, 3)
void gru_fused(const float* __restrict__ Hin, float* __restrict__ Hout,
               const uint2* __restrict__ wcF, const uint2* __restrict__ whhF,
               const float* __restrict__ bih, const float* __restrict__ bhh,
               const int* __restrict__ rowptrB, size_t hinStride){
    extern __shared__ char sm[];
    uint4*   sAg   = (uint4*)sm;              // fp16 frags G: 512 uint4 (8KB), live thru MMA
    uint4*   sH    = (uint4*)(sm + 8192);     // fp16 frags h (8KB), live thru MMA
    float*   sHval = (float*)(sm + 16384);    // 32*128 fp32 (16KB), live to end
    float*   sAval = (float*)(sm + 32768);    // 16KB staging; dead after pack
    __half2* sGr   = (__half2*)(sm + 32768);  // gate r (8KB) overlays sAval
    __half2* sGz   = (__half2*)(sm + 40960);  // gate z (8KB) overlays sAval
    __half2* sGi   = (__half2*)(sm + 49152);  // gate inn (8KB)
    __half2* sGn   = (__half2*)(sm + 57344);  // gate hn (8KB)
    float*   sbias = (float*)(sm + 65536);    // 512 f (2KB)  -> total 67584
    int tid = threadIdx.x, wid = tid >> 5, lane = tid & 31;
    int gid = lane >> 2, tig = lane & 3;

    int v   = blockIdx.x / GRU_GRID;
    int blk = blockIdx.x % GRU_GRID;
    int m0 = blk*32;
    const float* Hsrc = Hin + (size_t)v * hinStride;
    Hout   += (size_t)v * NN * HH;
    wcF    += (size_t)v * 49152;
    whhF   += (size_t)v * 12288;
    bih    += v * H3;
    bhh    += v * H3;
    const int* rowptr = rowptrB + v * NN;

    if (tid < 128){
        sbias[tid]     = bih[tid]     + bhh[tid];
        sbias[128+tid] = bih[128+tid] + bhh[128+tid];
        sbias[256+tid] = bih[256+tid];
        sbias[384+tid] = bhh[256+tid];
    }
    // h tile (32 rows)
    for (int it = tid; it < 32*32; it += 256){
        int r = it >> 5, c4 = it & 31;
        float4 hv = make_float4(0.f,0.f,0.f,0.f);
        if (m0 + r < NN) hv = *(const float4*)(Hsrc + (size_t)(m0+r)*HH + c4*4);
        *(float4*)(sHval + r*128 + c4*4) = hv;
    }
    // CSR gather (4 rows per warp)
    for (int rr = wid; rr < 32; rr += 8){
        int grow = m0 + rr;
        float4 acc = make_float4(0.f,0.f,0.f,0.f);
        if (grow < NN){
            int s = rowptr[grow], e = rowptr[grow + 1];
            int idx = s;
            while (idx + 4 <= e){
                int a0 = g_csrsrc[idx], a1 = g_csrsrc[idx+1];
                int a2 = g_csrsrc[idx+2], a3 = g_csrsrc[idx+3];
                float4 v0 = *(const float4*)(Hsrc + (size_t)a0*HH + lane*4);
                float4 v1 = *(const float4*)(Hsrc + (size_t)a1*HH + lane*4);
                float4 v2 = *(const float4*)(Hsrc + (size_t)a2*HH + lane*4);
                float4 v3 = *(const float4*)(Hsrc + (size_t)a3*HH + lane*4);
                acc.x += v0.x + v1.x + v2.x + v3.x;
                acc.y += v0.y + v1.y + v2.y + v3.y;
                acc.z += v0.z + v1.z + v2.z + v3.z;
                acc.w += v0.w + v1.w + v2.w + v3.w;
                idx += 4;
            }
            while (idx < e){
                int a0 = g_csrsrc[idx];
                float4 v0 = *(const float4*)(Hsrc + (size_t)a0*HH + lane*4);
                acc.x += v0.x; acc.y += v0.y; acc.z += v0.z; acc.w += v0.w;
                idx++;
            }
        }
        *(float4*)(sAval + rr*128 + lane*4) = acc;
    }
    __syncthreads();
    // pack G + h into fp16 fragments (2 mt x 8 kt x 32 lanes = 512 items)
    for (int it = tid; it < 512; it += 256){
        int mt = it >> 8, kt = (it >> 5) & 7, ln = it & 31;
        int g = ln >> 2, tg = ln & 3;
        int r0 = mt*16 + g, r1 = r0 + 8;
        int k = kt*16 + tg*2;
        float2 a00 = *(const float2*)(sAval + r0*128 + k);
        float2 a01 = *(const float2*)(sAval + r0*128 + k + 8);
        float2 a10 = *(const float2*)(sAval + r1*128 + k);
        float2 a11 = *(const float2*)(sAval + r1*128 + k + 8);
        sAg[(mt*8 + kt)*32 + ln] = make_uint4(packh(a00.x, a00.y), packh(a10.x, a10.y),
                                              packh(a01.x, a01.y), packh(a11.x, a11.y));
        float2 h00 = *(const float2*)(sHval + r0*128 + k);
        float2 h01 = *(const float2*)(sHval + r0*128 + k + 8);
        float2 h10 = *(const float2*)(sHval + r1*128 + k);
        float2 h11 = *(const float2*)(sHval + r1*128 + k + 8);
        sH[(mt*8 + kt)*32 + ln] = make_uint4(packh(h00.x, h00.y), packh(h10.x, h10.y),
                                             packh(h01.x, h01.y), packh(h11.x, h11.y));
    }
    __syncthreads();   // sAval dead from here; gate buffers r,z may overwrite it

    // MMA phase: warp = (gate g, col slice sub); nt in 2 halves (acc 32 regs)
    int g = wid >> 1, sub = wid & 1;
    __half2* gbuf = (g == 0) ? sGr : (g == 1) ? sGz : (g == 2) ? sGi : sGn;
    for (int half = 0; half < 2; half++){
        float acc[2][4][4];
        #pragma unroll
        for (int mt = 0; mt < 2; mt++)
            #pragma unroll
            for (int nt = 0; nt < 4; nt++)
                #pragma unroll
                for (int q = 0; q < 4; q++) acc[mt][nt][q] = 0.f;
        if (g == 0){ GPASS_H(sAg, wcF, 0, half, acc); GPASS_H(sH, whhF, 0, half, acc); }
        else if (g == 1){ GPASS_H(sAg, wcF, 1, half, acc); GPASS_H(sH, whhF, 1, half, acc); }
        else if (g == 2){ GPASS_H(sAg, wcF, 2, half, acc); }
        else            { GPASS_H(sH, whhF, 2, half, acc); }
        GDUMP(gbuf, half, acc);
    }
    __syncthreads();

    // epilogue: warp per row (4 rows/warp), lane = 4 cols
    for (int rr = wid; rr < 32; rr += 8){
        int grow = m0 + rr;
        if (grow >= NN) continue;
        int col = lane*4, c2 = lane*2;
        float2 r01 = gread(sGr, rr, c2), r23 = gread(sGr, rr, c2+1);
        float2 z01 = gread(sGz, rr, c2), z23 = gread(sGz, rr, c2+1);
        float2 i01 = gread(sGi, rr, c2), i23 = gread(sGi, rr, c2+1);
        float2 n01 = gread(sGn, rr, c2), n23 = gread(sGn, rr, c2+1);
        float4 h4 = *(float4*)(sHval + rr*128 + col);
        float4 br = *(float4*)(sbias + col);
        float4 bz = *(float4*)(sbias + 128 + col);
        float4 bi = *(float4*)(sbias + 256 + col);
        float4 bh = *(float4*)(sbias + 384 + col);
        float4 o;
        {
            float r_ = sigm(r01.x + br.x), z_ = sigm(z01.x + bz.x);
            float n_ = tanhf(i01.x + bi.x + r_*(n01.x + bh.x));
            o.x = (1.f - z_)*n_ + z_*h4.x;
        }
        {
            float r_ = sigm(r01.y + br.y), z_ = sigm(z01.y + bz.y);
            float n_ = tanhf(i01.y + bi.y + r_*(n01.y + bh.y));
            o.y = (1.f - z_)*n_ + z_*h4.y;
        }
        {
            float r_ = sigm(r23.x + br.z), z_ = sigm(z23.x + bz.z);
            float n_ = tanhf(i23.x + bi.z + r_*(n23.x + bh.z));
            o.z = (1.f - z_)*n_ + z_*h4.z;
        }
        {
            float r_ = sigm(r23.y + br.w), z_ = sigm(z23.y + bz.w);
            float n_ = tanhf(i23.y + bi.w + r_*(n23.y + bh.w));
            o.w = (1.f - z_)*n_ + z_*h4.w;
        }
        *(float4*)(Hout + (size_t)grow*HH + col) = o;
    }
}

// ---------------- LN + GELU after projection (warp per row) ----------------
__global__ void ln_gelu(const float* __restrict__ lnw, const float* __restrict__ lnb){
    int gw = (blockIdx.x*blockDim.x + threadIdx.x) >> 5;
    if (gw >= NN) return;
    int lane = threadIdx.x & 31;
    float xv[4], s = 0.f, s2 = 0.f;
    #pragma unroll
    for (int i = 0; i < 4; i++){
        xv[i] = g_proj[(size_t)gw*HH + lane + 32*i];
        s += xv[i]; s2 += xv[i]*xv[i];
    }
    #pragma unroll
    for (int o = 16; o; o >>= 1){
        s  += __shfl_xor_sync(0xffffffffu, s,  o);
        s2 += __shfl_xor_sync(0xffffffffu, s2, o);
    }
    float mu = s*(1.f/HH), var = s2*(1.f/HH) - mu*mu;
    float rstd = rsqrtf(var + 1e-5f);
    #pragma unroll
    for (int i = 0; i < 4; i++){
        int j = lane + 32*i;
        float y = (xv[i] - mu)*rstd*lnw[j] + lnb[j];
        g_h0[(size_t)gw*HH + j] = 0.5f*y*(1.f + erff(y*0.7071067811865476f));
    }
}

// ---------------- fused: per-view LN + residual + attention ----------
__global__ void ln_attn(const float* __restrict__ hall,
                        const float* __restrict__ vlnw, const float* __restrict__ vlnb){
    int gw = (blockIdx.x*blockDim.x + threadIdx.x) >> 5;
    if (gw >= NN) return;
    int lane = threadIdx.x & 31;
    float h0v[4], qkv[4];
    #pragma unroll
    for (int i = 0; i < 4; i++){
        h0v[i] = g_h0[(size_t)gw*HH + lane + 32*i];
        qkv[i] = g_qk[(size_t)gw*HH + lane + 32*i];
    }
    float y[4][4], sc[4];
    #pragma unroll
    for (int v = 0; v < 4; v++){
        float xv[4], s = 0.f, s2 = 0.f;
        #pragma unroll
        for (int i = 0; i < 4; i++){
            xv[i] = hall[((size_t)v*NN + gw)*HH + lane + 32*i];
            s += xv[i]; s2 += xv[i]*xv[i];
        }
        #pragma unroll
        for (int o = 16; o; o >>= 1){
            s  += __shfl_xor_sync(0xffffffffu, s,  o);
            s2 += __shfl_xor_sync(0xffffffffu, s2, o);
        }
        float mu = s*(1.f/HH), var = s2*(1.f/HH) - mu*mu;
        float rstd = rsqrtf(var + 1e-5f);
        float p = 0.f;
        #pragma unroll
        for (int i = 0; i < 4; i++){
            int j = lane + 32*i;
            y[v][i] = (xv[i] - mu)*rstd*vlnw[v*HH + j] + vlnb[v*HH + j] + h0v[i];
            p += qkv[i]*y[v][i];
        }
        #pragma unroll
        for (int o = 16; o; o >>= 1) p += __shfl_xor_sync(0xffffffffu, p, o);
        sc[v] = p * 0.08838834764831845f;
    }
    float mx = fmaxf(fmaxf(sc[0], sc[1]), fmaxf(sc[2], sc[3]));
    float ex[4], sum = 0.f;
    #pragma unroll
    for (int v = 0; v < 4; v++){ ex[v] = expf(sc[v] - mx); sum += ex[v]; }
    float inv = 1.f/sum;
    #pragma unroll
    for (int i = 0; i < 4; i++){
        float o = 0.f;
        #pragma unroll
        for (int v = 0; v < 4; v++) o += ex[v]*inv*y[v][i];
        g_fused[(size_t)gw*HH + lane + 32*i] = o;
    }
}

// ---------------- pooling ----------------
__global__ void pool_init(){
    int i = blockIdx.x*blockDim.x + threadIdx.x;
    if (i < BB*HH){ g_psum[i] = 0.f; g_pmax[i] = 0u; }
    if (i < BB) g_cnt[i] = 0.f;
}
__global__ void pool_acc(const int* __restrict__ batch){
    int j = threadIdx.x;
    int n0 = blockIdx.x * 64;
    int cur = -1; float sum = 0.f, mx = -1e30f; int cnt = 0;
    for (int t = 0; t < 64; t++){
        int n = n0 + t;
        if (n >= NN) break;
        int b = batch[n];
        if (b != cur){
            if (cur >= 0){
                atomicAdd(&g_psum[cur*HH + j], sum);
                atomicMax(&g_pmax[cur*HH + j], fenc(mx));
                if (j == 0) atomicAdd(&g_cnt[cur], (float)cnt);
            }
            cur = b; sum = 0.f; mx = -1e30f; cnt = 0;
        }
        float f = g_fused[(size_t)n*HH + j];
        sum += f; mx = fmaxf(mx, f); cnt++;
    }
    if (cur >= 0){
        atomicAdd(&g_psum[cur*HH + j], sum);
        atomicMax(&g_pmax[cur*HH + j], fenc(mx));
        if (j == 0) atomicAdd(&g_cnt[cur], (float)cnt);
    }
}

// ---------------- classifier ----------------
__global__ void classifier(const float* __restrict__ c1w, const float* __restrict__ c1b,
                           const float* __restrict__ c2w, const float* __restrict__ c2b,
                           const float* __restrict__ c3w, const float* __restrict__ c3b,
                           float* __restrict__ out){
    __shared__ float gsh[2*HH], h1[HH], h2[64];
    int b = blockIdx.x, j = threadIdx.x;
    float cnt = fmaxf(g_cnt[b], 1.f);
    gsh[j]      = g_psum[b*HH + j] / cnt;
    gsh[HH + j] = fdec(g_pmax[b*HH + j]);
    __syncthreads();
    float a = c1b[j];
    for (int k = 0; k < 2*HH; k++) a += gsh[k]*c1w[k*HH + j];
    h1[j] = fmaxf(a, 0.f);
    __syncthreads();
    if (j < 64){
        float a2 = c2b[j];
        for (int k = 0; k < HH; k++) a2 += h1[k]*c2w[k*64 + j];
        h2[j] = fmaxf(a2, 0.f);
    }
    __syncthreads();
    if (j == 0){
        float o = c3b[0];
        for (int k = 0; k < 64; k++) o += h2[k]*c3w[k];
        out[b] = o;
    }
}

// ---------------- launch ----------------
extern "C" void kernel_launch(void* const* d_in, const int* in_sizes, int n_in,
                              void* d_out, int out_size){
    (void)in_sizes; (void)n_in; (void)out_size;
    const float* x      = (const float*)d_in[0];
    const int*   ei     = (const int*)  d_in[1];
    const int*   et     = (const int*)  d_in[2];
    const int*   batch  = (const int*)  d_in[3];
    const float* proj_w = (const float*)d_in[4];
    const float* proj_b = (const float*)d_in[5];
    const float* ln0w   = (const float*)d_in[6];
    const float* ln0b   = (const float*)d_in[7];
    const float* ggnn   = (const float*)d_in[8];
    const float* wih    = (const float*)d_in[9];
    const float* whh    = (const float*)d_in[10];
    const float* bih    = (const float*)d_in[11];
    const float* bhh    = (const float*)d_in[12];
    const float* vlnw   = (const float*)d_in[13];
    const float* vlnb   = (const float*)d_in[14];
    const float* qw     = (const float*)d_in[15];
    const float* qb     = (const float*)d_in[16];
    const float* kw     = (const float*)d_in[17];
    /* kb unused: softmax-invariant */
    const float* c1w    = (const float*)d_in[19];
    const float* c1b    = (const float*)d_in[20];
    const float* c2w    = (const float*)d_in[21];
    const float* c2b    = (const float*)d_in[22];
    const float* c3w    = (const float*)d_in[23];
    const float* c3b    = (const float*)d_in[24];
    float* out = (float*)d_out;

    float *p_h0, *p_hallA, *p_hallB, *p_proj, *p_q, *p_qk;
    uint2 *p_frag16, *p_imgW, *p_imgU;
    int* p_rowptr;
    cudaGetSymbolAddress((void**)&p_h0,    g_h0);
    cudaGetSymbolAddress((void**)&p_hallA, g_hallA);
    cudaGetSymbolAddress((void**)&p_hallB, g_hallB);
    cudaGetSymbolAddress((void**)&p_proj,  g_proj);
    cudaGetSymbolAddress((void**)&p_q,     g_q);
    cudaGetSymbolAddress((void**)&p_qk,    g_qk);
    cudaGetSymbolAddress((void**)&p_frag16, g_frag16);
    cudaGetSymbolAddress((void**)&p_imgW,  g_imgW);
    cudaGetSymbolAddress((void**)&p_imgU,  g_imgU);
    cudaGetSymbolAddress((void**)&p_rowptr, g_rowptr);

    const int GRU_SMEM = 67584;   // 66KB -> 3 CTAs/SM
    cudaFuncSetAttribute(gru_fused, cudaFuncAttributeMaxDynamicSharedMemorySize, GRU_SMEM);
    const int WC_SMEM = (2*128*129 + 128*128) * 4;
    cudaFuncSetAttribute(wcomb_prep, cudaFuncAttributeMaxDynamicSharedMemorySize, WC_SMEM);

    const size_t NH = (size_t)NN*HH;

    csr_zero<<<(SEGN + 255)/256, 256>>>();
    csr_count<<<(EE + 255)/256, 256>>>(ei, et);
    csr_scan1<<<SCAN_BLKS, 1024>>>();
    csr_scan2<<<1, 1024>>>();
    csr_scan3<<<(SEGN + 255)/256, 256>>>();
    csr_fill<<<(EE + 255)/256, 256>>>(ei, et);

    prep_frags16<<<(FRAG_TOTAL + 255)/256, 256>>>(proj_w, qw, kw);
    prep_whh16<<<(4*12288 + 255)/256, 256>>>(whh);
    wcomb_prep<<<dim3(16,3), 256, WC_SMEM>>>(ggnn, wih);

    gemm_mma16<<<dim3(MT,1), 256>>>(x, INF_, NN, p_frag16 + OFF_PROJ, 16, 32, proj_b, p_proj, HH, 0);
    ln_gelu<<<(NN*32 + 255)/256, 256>>>(ln0w, ln0b);

    gemm_mma16<<<dim3(MT,1), 256>>>(p_h0, HH, NN, p_frag16 + OFF_QW, 16, 8, qb, p_q, HH, 1);
    gemm_mma16<<<dim3(MT,1), 256>>>(p_q, HH, NN, p_frag16 + OFF_KWT, 16, 8, nullptr, p_qk, HH, 0);

    float* bufs[2] = { p_hallA, p_hallB };
    const float* hin = p_h0;
    size_t hinStride = 0;
    float* hout = p_hallA;
    for (int i = 0; i < 4; i++){
        gru_fused<<<4*GRU_GRID, 256, GRU_SMEM>>>(hin, hout,
            p_imgW + (size_t)i*12288, p_imgU,
            bih, bhh, p_rowptr, hinStride);
        hin = hout;
        hinStride = NH;
        hout = bufs[(i + 1) & 1];
    }
    const float* hfinal = hin;

    ln_attn<<<(NN*32 + 255)/256, 256>>>(hfinal, vlnw, vlnb);

    pool_init<<<(BB*HH + 255)/256, 256>>>();
    pool_acc<<<(NN + 63)/64, 128>>>(batch);
    classifier<<<BB, 128>>>(c1w, c1b, c2w, c2b, c3w, c3b, out);
}